// round 1
// baseline (speedup 1.0000x reference)
#include <cuda_runtime.h>
#include <math.h>

#define T_TOK 1024
#define DIN   2048
#define NH    32
#define NKV   8
#define HD    64

// Scratch (static device globals — no allocation allowed)
__device__ float g_q[T_TOK * NH * HD];
__device__ float g_k[T_TOK * NKV * HD];
__device__ float g_v[T_TOK * NKV * HD];
__device__ float g_att[T_TOK * NH * HD];

// ---------------------------------------------------------------------------
// C[M,N] = A[M,K] * B[N,K]^T   (row-major A [M,K], B [N,K])
// 64x64 block tile, 16-deep k step, 256 threads, 4x4 per-thread micro-tile.
// Smem stored k-major (transposed) so inner loop is 2x LDS.128 + 16 FFMA.
// ---------------------------------------------------------------------------
__global__ __launch_bounds__(256) void gemm_nt(const float* __restrict__ A,
                                               const float* __restrict__ B,
                                               float* __restrict__ C,
                                               int M, int N, int K) {
    __shared__ float As[16][68];
    __shared__ float Bs[16][68];
    const int tid = threadIdx.x;
    const int tx = tid & 15;
    const int ty = tid >> 4;
    const int bm = blockIdx.y * 64;
    const int bn = blockIdx.x * 64;

    float acc[4][4] = {};

    for (int k0 = 0; k0 < K; k0 += 16) {
#pragma unroll
        for (int l = 0; l < 4; l++) {
            int idx = tid + l * 256;
            int kk = idx & 15;
            int r  = idx >> 4;
            As[kk][r] = A[(size_t)(bm + r) * K + (k0 + kk)];
            Bs[kk][r] = B[(size_t)(bn + r) * K + (k0 + kk)];
        }
        __syncthreads();
#pragma unroll
        for (int kk = 0; kk < 16; kk++) {
            float4 a = *(const float4*)&As[kk][ty * 4];
            float4 b = *(const float4*)&Bs[kk][tx * 4];
            float av[4] = {a.x, a.y, a.z, a.w};
            float bv[4] = {b.x, b.y, b.z, b.w};
#pragma unroll
            for (int i = 0; i < 4; i++)
#pragma unroll
                for (int j = 0; j < 4; j++)
                    acc[i][j] += av[i] * bv[j];
        }
        __syncthreads();
    }

#pragma unroll
    for (int i = 0; i < 4; i++) {
        float4 o = make_float4(acc[i][0], acc[i][1], acc[i][2], acc[i][3]);
        *(float4*)&C[(size_t)(bm + ty * 4 + i) * N + bn + tx * 4] = o;
    }
}

// ---------------------------------------------------------------------------
// In-place RMSNorm + RoPE. One warp per (token, head). HD=64 -> 2 elems/lane.
// rotated = concat(-x2, x1); out = x*cos + rotated*sin
// ---------------------------------------------------------------------------
__global__ __launch_bounds__(256) void norm_rope(float* __restrict__ buf,
                                                 const float* __restrict__ w,
                                                 const float* __restrict__ cosb,
                                                 const float* __restrict__ sinb,
                                                 int nheads) {
    const int t = blockIdx.x;
    const int warp = threadIdx.x >> 5;
    const int lane = threadIdx.x & 31;
    const int h = blockIdx.y * 8 + warp;
    if (h >= nheads) return;

    float* p = buf + (size_t)t * nheads * HD + h * HD;
    float a = p[lane];        // d in [0,32)
    float b = p[lane + 32];   // d in [32,64)

    float ss = a * a + b * b;
#pragma unroll
    for (int o = 16; o; o >>= 1) ss += __shfl_xor_sync(0xffffffffu, ss, o);
    float inv = rsqrtf(ss * (1.0f / HD) + 1e-6f);

    a *= inv * w[lane];
    b *= inv * w[lane + 32];

    float c0 = cosb[t * HD + lane];
    float s0 = sinb[t * HD + lane];
    float c1 = cosb[t * HD + lane + 32];
    float s1 = sinb[t * HD + lane + 32];

    p[lane]      = a * c0 - b * s0;   // x1*cos - x2*sin
    p[lane + 32] = b * c1 + a * s1;   // x2*cos + x1*sin
}

// ---------------------------------------------------------------------------
// Flash-style causal GQA attention, fp32, online softmax.
// Grid: (qtile=16, head=32). Block 256 threads (16x16), 4x4 micro-tiles.
// Smem (dynamic, 68KB): Qs/Ks d-major [64][68], Vs c-major [64][68],
// Ps c-major [64][68] (P transposed for the PV GEMM).
// ---------------------------------------------------------------------------
#define APITCH 68
__global__ __launch_bounds__(256) void attn_kernel(const float* __restrict__ q,
                                                   const float* __restrict__ k,
                                                   const float* __restrict__ v,
                                                   float* __restrict__ out) {
    extern __shared__ float sm[];
    float* Qs = sm;                   // Qs[d*68 + r]
    float* Ks = sm + 64 * APITCH;     // Ks[d*68 + c]
    float* Vs = sm + 2 * 64 * APITCH; // Vs[c*68 + d]
    float* Ps = sm + 3 * 64 * APITCH; // Ps[c*68 + r]

    const int qt = blockIdx.x;        // query tile (64 rows)
    const int h  = blockIdx.y;        // head
    const int kvh = h >> 2;           // GROUP = 4
    const int tid = threadIdx.x;
    const int tx = tid & 15;
    const int ty = tid >> 4;

    // Load Q tile (transposed: d-major)
#pragma unroll
    for (int l = 0; l < 16; l++) {
        int idx = tid + l * 256;
        int d = idx & 63;
        int r = idx >> 6;
        Qs[d * APITCH + r] =
            q[(size_t)(qt * 64 + r) * (NH * HD) + h * HD + d];
    }

    float m_[4], l_[4], O[4][4];
#pragma unroll
    for (int i = 0; i < 4; i++) {
        m_[i] = -1e30f;
        l_[i] = 0.0f;
#pragma unroll
        for (int j = 0; j < 4; j++) O[i][j] = 0.0f;
    }

    for (int s = 0; s <= qt; s++) {
        __syncthreads();  // previous PV reads / Q load complete before overwrite
        // Load K (transposed) and V (natural)
#pragma unroll
        for (int l = 0; l < 16; l++) {
            int idx = tid + l * 256;
            int d = idx & 63;
            int c = idx >> 6;
            size_t g = (size_t)(s * 64 + c) * (NKV * HD) + kvh * HD + d;
            Ks[d * APITCH + c] = k[g];
            Vs[c * APITCH + d] = v[g];
        }
        __syncthreads();

        // S = Q K^T
        float sreg[4][4] = {};
#pragma unroll
        for (int d = 0; d < 64; d++) {
            float4 qa = *(const float4*)&Qs[d * APITCH + ty * 4];
            float4 kb = *(const float4*)&Ks[d * APITCH + tx * 4];
            float qv[4] = {qa.x, qa.y, qa.z, qa.w};
            float kv[4] = {kb.x, kb.y, kb.z, kb.w};
#pragma unroll
            for (int i = 0; i < 4; i++)
#pragma unroll
                for (int j = 0; j < 4; j++)
                    sreg[i][j] += qv[i] * kv[j];
        }

        // scale + causal mask (diag tile only)
        const bool diag = (s == qt);
#pragma unroll
        for (int i = 0; i < 4; i++)
#pragma unroll
            for (int j = 0; j < 4; j++) {
                float val = sreg[i][j] * 0.125f;  // 1/sqrt(64)
                if (diag && (tx * 4 + j > ty * 4 + i)) val = -1e30f;
                sreg[i][j] = val;
            }

        // Online softmax update (row reductions across the 16 tx lanes;
        // lane = (ty&1)*16 + tx, so xor-8/4/2/1 stays within the group)
#pragma unroll
        for (int i = 0; i < 4; i++) {
            float rm = fmaxf(fmaxf(sreg[i][0], sreg[i][1]),
                             fmaxf(sreg[i][2], sreg[i][3]));
#pragma unroll
            for (int o = 8; o; o >>= 1)
                rm = fmaxf(rm, __shfl_xor_sync(0xffffffffu, rm, o));
            float newm = fmaxf(m_[i], rm);
            float corr = __expf(m_[i] - newm);
            float rsum = 0.0f;
#pragma unroll
            for (int j = 0; j < 4; j++) {
                float p = __expf(sreg[i][j] - newm);
                sreg[i][j] = p;
                rsum += p;
            }
#pragma unroll
            for (int o = 8; o; o >>= 1)
                rsum += __shfl_xor_sync(0xffffffffu, rsum, o);
            l_[i] = l_[i] * corr + rsum;
            m_[i] = newm;
#pragma unroll
            for (int j = 0; j < 4; j++) O[i][j] *= corr;
        }

        // Write P transposed (c-major) for the PV GEMM
#pragma unroll
        for (int i = 0; i < 4; i++)
#pragma unroll
            for (int j = 0; j < 4; j++)
                Ps[(tx * 4 + j) * APITCH + ty * 4 + i] = sreg[i][j];
        __syncthreads();

        // O += P V
#pragma unroll
        for (int c = 0; c < 64; c++) {
            float4 pa = *(const float4*)&Ps[c * APITCH + ty * 4];
            float4 vb = *(const float4*)&Vs[c * APITCH + tx * 4];
            float pv[4] = {pa.x, pa.y, pa.z, pa.w};
            float vv[4] = {vb.x, vb.y, vb.z, vb.w};
#pragma unroll
            for (int i = 0; i < 4; i++)
#pragma unroll
                for (int j = 0; j < 4; j++)
                    O[i][j] += pv[i] * vv[j];
        }
    }

    // Epilogue: normalize and write [token, h*64 + d]
#pragma unroll
    for (int i = 0; i < 4; i++) {
        float inv = 1.0f / l_[i];
        float4 o = make_float4(O[i][0] * inv, O[i][1] * inv,
                               O[i][2] * inv, O[i][3] * inv);
        *(float4*)&out[(size_t)(qt * 64 + ty * 4 + i) * (NH * HD) +
                       h * HD + tx * 4] = o;
    }
}

// ---------------------------------------------------------------------------
// Launch: QKV GEMMs -> norm+rope -> attention -> out proj
// Inputs: 0=x 1=scale_x 2=mask 3=cos 4=scale_cos 5=sin 6=scale_sin
//         7=Wq 8=Wk 9=Wv 10=Wo 11=q_norm_w 12=k_norm_w
// ---------------------------------------------------------------------------
extern "C" void kernel_launch(void* const* d_in, const int* in_sizes, int n_in,
                              void* d_out, int out_size) {
    const float* x    = (const float*)d_in[0];
    const float* cosb = (const float*)d_in[3];
    const float* sinb = (const float*)d_in[5];
    const float* Wq   = (const float*)d_in[7];
    const float* Wk   = (const float*)d_in[8];
    const float* Wv   = (const float*)d_in[9];
    const float* Wo   = (const float*)d_in[10];
    const float* qw   = (const float*)d_in[11];
    const float* kw   = (const float*)d_in[12];
    float* out = (float*)d_out;

    float *qb, *kb, *vb, *ab;
    cudaGetSymbolAddress((void**)&qb, g_q);
    cudaGetSymbolAddress((void**)&kb, g_k);
    cudaGetSymbolAddress((void**)&vb, g_v);
    cudaGetSymbolAddress((void**)&ab, g_att);

    // QKV projections
    gemm_nt<<<dim3(32, 16), 256>>>(x, Wq, qb, T_TOK, NH * HD, DIN);
    gemm_nt<<<dim3(8, 16), 256>>>(x, Wk, kb, T_TOK, NKV * HD, DIN);
    gemm_nt<<<dim3(8, 16), 256>>>(x, Wv, vb, T_TOK, NKV * HD, DIN);

    // RMSNorm + RoPE (in place)
    norm_rope<<<dim3(T_TOK, 4), 256>>>(qb, qw, cosb, sinb, NH);
    norm_rope<<<dim3(T_TOK, 1), 256>>>(kb, kw, cosb, sinb, NKV);

    // Causal GQA attention
    const int smem = 4 * 64 * APITCH * (int)sizeof(float);  // 69632 B
    cudaFuncSetAttribute(attn_kernel,
                         cudaFuncAttributeMaxDynamicSharedMemorySize, smem);
    attn_kernel<<<dim3(16, 32), 256, smem>>>(qb, kb, vb, ab);

    // Output projection
    gemm_nt<<<dim3(32, 16), 256>>>(ab, Wo, out, T_TOK, DIN, NH * HD);
}

// round 2
// speedup vs baseline: 2.0385x; 2.0385x over previous
#include <cuda_runtime.h>
#include <stdint.h>
#include <math.h>

#define T_TOK 1024
#define DIN   2048
#define NH    32
#define NKV   8
#define HD    64

// Scratch (static device globals — no allocation allowed)
__device__ float g_q[T_TOK * NH * HD];
__device__ float g_k[T_TOK * NKV * HD];
__device__ float g_v[T_TOK * NKV * HD];
__device__ float g_att[T_TOK * NH * HD];

// ---------------------------------------------------------------------------
// tf32 helpers
// ---------------------------------------------------------------------------
__device__ __forceinline__ uint32_t f2tf32(float f) {
    uint32_t r;
    asm("cvt.rna.tf32.f32 %0, %1;" : "=r"(r) : "f"(f));
    return r;
}

__device__ __forceinline__ void mma_tf32(float* c, const uint32_t* a,
                                         const uint32_t* b) {
    asm volatile(
        "mma.sync.aligned.m16n8k8.row.col.f32.tf32.tf32.f32 "
        "{%0,%1,%2,%3},{%4,%5,%6,%7},{%8,%9},{%0,%1,%2,%3};"
        : "+f"(c[0]), "+f"(c[1]), "+f"(c[2]), "+f"(c[3])
        : "r"(a[0]), "r"(a[1]), "r"(a[2]), "r"(a[3]), "r"(b[0]), "r"(b[1]));
}

// ---------------------------------------------------------------------------
// C[M,N] = A[M,K] * B[N,K]^T  via tf32 tensor-core mma.
// Block tile 128x64, 256 threads (8 warps, 4 in M x 2 in N), warp tile 32x32.
// k-chunk 32 per smem stage; smem pitch 36 -> conflict-free fragment loads.
// Register-prefetch pipeline on global loads.
// Requires: M%128==0, N%64==0, K%32==0.
// ---------------------------------------------------------------------------
__global__ __launch_bounds__(256) void gemm_tf32(const float* __restrict__ A,
                                                 const float* __restrict__ B,
                                                 float* __restrict__ C,
                                                 int M, int N, int K) {
    __shared__ uint32_t As[128][36];
    __shared__ uint32_t Bs[64][36];

    const int tid  = threadIdx.x;
    const int lane = tid & 31;
    const int warp = tid >> 5;
    const int g    = lane >> 2;   // group id (0..7)
    const int tq   = lane & 3;    // thread-in-group (0..3)
    const int wm   = warp & 3;    // warp m index (0..3)
    const int wn   = warp >> 2;   // warp n index (0..1)
    const int bm   = blockIdx.y * 128;
    const int bn   = blockIdx.x * 64;

    // global-load prefetch registers (A: 4 x float4, B: 2 x float4)
    float4 pa[4], pb[2];
    const int arow[4] = {(tid + 0) >> 3, (tid + 256) >> 3,
                         (tid + 512) >> 3, (tid + 768) >> 3};
    const int ac4 = tid & 7;
    const int brow[2] = {(tid + 0) >> 3, (tid + 256) >> 3};

    auto load_global = [&](int k0) {
#pragma unroll
        for (int l = 0; l < 4; l++)
            pa[l] = *(const float4*)&A[(size_t)(bm + arow[l]) * K + k0 + ac4 * 4];
#pragma unroll
        for (int l = 0; l < 2; l++)
            pb[l] = *(const float4*)&B[(size_t)(bn + brow[l]) * K + k0 + ac4 * 4];
    };
    auto store_smem = [&]() {
#pragma unroll
        for (int l = 0; l < 4; l++) {
            uint32_t* d = &As[arow[l]][ac4 * 4];
            d[0] = f2tf32(pa[l].x); d[1] = f2tf32(pa[l].y);
            d[2] = f2tf32(pa[l].z); d[3] = f2tf32(pa[l].w);
        }
#pragma unroll
        for (int l = 0; l < 2; l++) {
            uint32_t* d = &Bs[brow[l]][ac4 * 4];
            d[0] = f2tf32(pb[l].x); d[1] = f2tf32(pb[l].y);
            d[2] = f2tf32(pb[l].z); d[3] = f2tf32(pb[l].w);
        }
    };

    float acc[2][4][4];
#pragma unroll
    for (int mi = 0; mi < 2; mi++)
#pragma unroll
        for (int ni = 0; ni < 4; ni++)
#pragma unroll
            for (int r = 0; r < 4; r++) acc[mi][ni][r] = 0.0f;

    const int nstages = K >> 5;
    load_global(0);
    store_smem();
    __syncthreads();

    for (int s = 0; s < nstages; s++) {
        if (s + 1 < nstages) load_global((s + 1) << 5);

#pragma unroll
        for (int ks = 0; ks < 4; ks++) {
            const int kb = ks * 8;
            uint32_t af[2][4];
#pragma unroll
            for (int mi = 0; mi < 2; mi++) {
                const int m = wm * 32 + mi * 16;
                af[mi][0] = As[m + g][kb + tq];
                af[mi][1] = As[m + 8 + g][kb + tq];
                af[mi][2] = As[m + g][kb + tq + 4];
                af[mi][3] = As[m + 8 + g][kb + tq + 4];
            }
            uint32_t bf[4][2];
#pragma unroll
            for (int ni = 0; ni < 4; ni++) {
                const int n = wn * 32 + ni * 8;
                bf[ni][0] = Bs[n + g][kb + tq];
                bf[ni][1] = Bs[n + g][kb + tq + 4];
            }
#pragma unroll
            for (int mi = 0; mi < 2; mi++)
#pragma unroll
                for (int ni = 0; ni < 4; ni++)
                    mma_tf32(acc[mi][ni], af[mi], bf[ni]);
        }

        if (s + 1 < nstages) {
            __syncthreads();
            store_smem();
            __syncthreads();
        }
    }

    // Epilogue: c0:(g, 2tq) c1:(g, 2tq+1) c2:(g+8, 2tq) c3:(g+8, 2tq+1)
#pragma unroll
    for (int mi = 0; mi < 2; mi++)
#pragma unroll
        for (int ni = 0; ni < 4; ni++) {
            const int row = bm + wm * 32 + mi * 16 + g;
            const int col = bn + wn * 32 + ni * 8 + tq * 2;
            *(float2*)&C[(size_t)row * N + col] =
                make_float2(acc[mi][ni][0], acc[mi][ni][1]);
            *(float2*)&C[(size_t)(row + 8) * N + col] =
                make_float2(acc[mi][ni][2], acc[mi][ni][3]);
        }
}

// ---------------------------------------------------------------------------
// In-place RMSNorm + RoPE. One warp per (token, head). HD=64 -> 2 elems/lane.
// ---------------------------------------------------------------------------
__global__ __launch_bounds__(256) void norm_rope(float* __restrict__ buf,
                                                 const float* __restrict__ w,
                                                 const float* __restrict__ cosb,
                                                 const float* __restrict__ sinb,
                                                 int nheads) {
    const int t = blockIdx.x;
    const int warp = threadIdx.x >> 5;
    const int lane = threadIdx.x & 31;
    const int h = blockIdx.y * 8 + warp;
    if (h >= nheads) return;

    float* p = buf + (size_t)t * nheads * HD + h * HD;
    float a = p[lane];
    float b = p[lane + 32];

    float ss = a * a + b * b;
#pragma unroll
    for (int o = 16; o; o >>= 1) ss += __shfl_xor_sync(0xffffffffu, ss, o);
    float inv = rsqrtf(ss * (1.0f / HD) + 1e-6f);

    a *= inv * w[lane];
    b *= inv * w[lane + 32];

    float c0 = cosb[t * HD + lane];
    float s0 = sinb[t * HD + lane];
    float c1 = cosb[t * HD + lane + 32];
    float s1 = sinb[t * HD + lane + 32];

    p[lane]      = a * c0 - b * s0;
    p[lane + 32] = b * c1 + a * s1;
}

// ---------------------------------------------------------------------------
// Flash-style causal GQA attention, fp32, online softmax (unchanged R1).
// ---------------------------------------------------------------------------
#define APITCH 68
__global__ __launch_bounds__(256) void attn_kernel(const float* __restrict__ q,
                                                   const float* __restrict__ k,
                                                   const float* __restrict__ v,
                                                   float* __restrict__ out) {
    extern __shared__ float sm[];
    float* Qs = sm;
    float* Ks = sm + 64 * APITCH;
    float* Vs = sm + 2 * 64 * APITCH;
    float* Ps = sm + 3 * 64 * APITCH;

    const int qt = blockIdx.x;
    const int h  = blockIdx.y;
    const int kvh = h >> 2;
    const int tid = threadIdx.x;
    const int tx = tid & 15;
    const int ty = tid >> 4;

#pragma unroll
    for (int l = 0; l < 16; l++) {
        int idx = tid + l * 256;
        int d = idx & 63;
        int r = idx >> 6;
        Qs[d * APITCH + r] =
            q[(size_t)(qt * 64 + r) * (NH * HD) + h * HD + d];
    }

    float m_[4], l_[4], O[4][4];
#pragma unroll
    for (int i = 0; i < 4; i++) {
        m_[i] = -1e30f;
        l_[i] = 0.0f;
#pragma unroll
        for (int j = 0; j < 4; j++) O[i][j] = 0.0f;
    }

    for (int s = 0; s <= qt; s++) {
        __syncthreads();
#pragma unroll
        for (int l = 0; l < 16; l++) {
            int idx = tid + l * 256;
            int d = idx & 63;
            int c = idx >> 6;
            size_t gdx = (size_t)(s * 64 + c) * (NKV * HD) + kvh * HD + d;
            Ks[d * APITCH + c] = k[gdx];
            Vs[c * APITCH + d] = v[gdx];
        }
        __syncthreads();

        float sreg[4][4] = {};
#pragma unroll
        for (int d = 0; d < 64; d++) {
            float4 qa = *(const float4*)&Qs[d * APITCH + ty * 4];
            float4 kb = *(const float4*)&Ks[d * APITCH + tx * 4];
            float qv[4] = {qa.x, qa.y, qa.z, qa.w};
            float kv[4] = {kb.x, kb.y, kb.z, kb.w};
#pragma unroll
            for (int i = 0; i < 4; i++)
#pragma unroll
                for (int j = 0; j < 4; j++)
                    sreg[i][j] += qv[i] * kv[j];
        }

        const bool diag = (s == qt);
#pragma unroll
        for (int i = 0; i < 4; i++)
#pragma unroll
            for (int j = 0; j < 4; j++) {
                float val = sreg[i][j] * 0.125f;
                if (diag && (tx * 4 + j > ty * 4 + i)) val = -1e30f;
                sreg[i][j] = val;
            }

#pragma unroll
        for (int i = 0; i < 4; i++) {
            float rm = fmaxf(fmaxf(sreg[i][0], sreg[i][1]),
                             fmaxf(sreg[i][2], sreg[i][3]));
#pragma unroll
            for (int o = 8; o; o >>= 1)
                rm = fmaxf(rm, __shfl_xor_sync(0xffffffffu, rm, o));
            float newm = fmaxf(m_[i], rm);
            float corr = __expf(m_[i] - newm);
            float rsum = 0.0f;
#pragma unroll
            for (int j = 0; j < 4; j++) {
                float p = __expf(sreg[i][j] - newm);
                sreg[i][j] = p;
                rsum += p;
            }
#pragma unroll
            for (int o = 8; o; o >>= 1)
                rsum += __shfl_xor_sync(0xffffffffu, rsum, o);
            l_[i] = l_[i] * corr + rsum;
            m_[i] = newm;
#pragma unroll
            for (int j = 0; j < 4; j++) O[i][j] *= corr;
        }

#pragma unroll
        for (int i = 0; i < 4; i++)
#pragma unroll
            for (int j = 0; j < 4; j++)
                Ps[(tx * 4 + j) * APITCH + ty * 4 + i] = sreg[i][j];
        __syncthreads();

#pragma unroll
        for (int c = 0; c < 64; c++) {
            float4 pa = *(const float4*)&Ps[c * APITCH + ty * 4];
            float4 vb = *(const float4*)&Vs[c * APITCH + tx * 4];
            float pv[4] = {pa.x, pa.y, pa.z, pa.w};
            float vv[4] = {vb.x, vb.y, vb.z, vb.w};
#pragma unroll
            for (int i = 0; i < 4; i++)
#pragma unroll
                for (int j = 0; j < 4; j++)
                    O[i][j] += pv[i] * vv[j];
        }
    }

#pragma unroll
    for (int i = 0; i < 4; i++) {
        float inv = 1.0f / l_[i];
        float4 o = make_float4(O[i][0] * inv, O[i][1] * inv,
                               O[i][2] * inv, O[i][3] * inv);
        *(float4*)&out[(size_t)(qt * 64 + ty * 4 + i) * (NH * HD) +
                       h * HD + tx * 4] = o;
    }
}

// ---------------------------------------------------------------------------
// Inputs: 0=x 1=scale_x 2=mask 3=cos 4=scale_cos 5=sin 6=scale_sin
//         7=Wq 8=Wk 9=Wv 10=Wo 11=q_norm_w 12=k_norm_w
// ---------------------------------------------------------------------------
extern "C" void kernel_launch(void* const* d_in, const int* in_sizes, int n_in,
                              void* d_out, int out_size) {
    const float* x    = (const float*)d_in[0];
    const float* cosb = (const float*)d_in[3];
    const float* sinb = (const float*)d_in[5];
    const float* Wq   = (const float*)d_in[7];
    const float* Wk   = (const float*)d_in[8];
    const float* Wv   = (const float*)d_in[9];
    const float* Wo   = (const float*)d_in[10];
    const float* qw   = (const float*)d_in[11];
    const float* kw   = (const float*)d_in[12];
    float* out = (float*)d_out;

    float *qb, *kb, *vb, *ab;
    cudaGetSymbolAddress((void**)&qb, g_q);
    cudaGetSymbolAddress((void**)&kb, g_k);
    cudaGetSymbolAddress((void**)&vb, g_v);
    cudaGetSymbolAddress((void**)&ab, g_att);

    // QKV projections (tf32 tensor cores)
    gemm_tf32<<<dim3(32, 8), 256>>>(x, Wq, qb, T_TOK, NH * HD, DIN);
    gemm_tf32<<<dim3(8, 8), 256>>>(x, Wk, kb, T_TOK, NKV * HD, DIN);
    gemm_tf32<<<dim3(8, 8), 256>>>(x, Wv, vb, T_TOK, NKV * HD, DIN);

    // RMSNorm + RoPE (in place)
    norm_rope<<<dim3(T_TOK, 4), 256>>>(qb, qw, cosb, sinb, NH);
    norm_rope<<<dim3(T_TOK, 1), 256>>>(kb, kw, cosb, sinb, NKV);

    // Causal GQA attention (fp32)
    const int smem = 4 * 64 * APITCH * (int)sizeof(float);
    cudaFuncSetAttribute(attn_kernel,
                         cudaFuncAttributeMaxDynamicSharedMemorySize, smem);
    attn_kernel<<<dim3(16, 32), 256, smem>>>(qb, kb, vb, ab);

    // Output projection (tf32 tensor cores)
    gemm_tf32<<<dim3(32, 8), 256>>>(ab, Wo, out, T_TOK, DIN, NH * HD);
}

// round 3
// speedup vs baseline: 2.6864x; 1.3178x over previous
#include <cuda_runtime.h>
#include <stdint.h>
#include <math.h>

#define T_TOK 1024
#define DIN   2048
#define NH    32
#define NKV   8
#define HD    64

__device__ float g_q[T_TOK * NH * HD];
__device__ float g_k[T_TOK * NKV * HD];
__device__ float g_v[T_TOK * NKV * HD];
__device__ float g_att[T_TOK * NH * HD];

// ---------------------------------------------------------------------------
// tf32 helpers
// ---------------------------------------------------------------------------
__device__ __forceinline__ uint32_t f2tf32(float f) {
    uint32_t r;
    asm("cvt.rna.tf32.f32 %0, %1;" : "=r"(r) : "f"(f));
    return r;
}

__device__ __forceinline__ void mma_tf32(float* c, const uint32_t* a,
                                         const uint32_t* b) {
    asm volatile(
        "mma.sync.aligned.m16n8k8.row.col.f32.tf32.tf32.f32 "
        "{%0,%1,%2,%3},{%4,%5,%6,%7},{%8,%9},{%0,%1,%2,%3};"
        : "+f"(c[0]), "+f"(c[1]), "+f"(c[2]), "+f"(c[3])
        : "r"(a[0]), "r"(a[1]), "r"(a[2]), "r"(a[3]), "r"(b[0]), "r"(b[1]));
}

// ---------------------------------------------------------------------------
// C[M,N] = A[M,K] * B[N,K]^T  via tf32 mma; 128x64 tile, 256 thr, 8 warps.
// Double-buffered smem (k-chunk 32), one __syncthreads per stage.
// ---------------------------------------------------------------------------
__global__ __launch_bounds__(256) void gemm_tf32(const float* __restrict__ A,
                                                 const float* __restrict__ B,
                                                 float* __restrict__ C,
                                                 int M, int N, int K) {
    extern __shared__ uint32_t sh[];
    uint32_t (*As)[36] = (uint32_t(*)[36])sh;               // [2*128][36]
    uint32_t (*Bs)[36] = (uint32_t(*)[36])(sh + 2 * 128 * 36);  // [2*64][36]

    const int tid  = threadIdx.x;
    const int lane = tid & 31;
    const int warp = tid >> 5;
    const int g    = lane >> 2;
    const int tq   = lane & 3;
    const int wm   = warp & 3;
    const int wn   = warp >> 2;
    const int bm   = blockIdx.y * 128;
    const int bn   = blockIdx.x * 64;

    float4 pa[4], pb[2];
    const int arow[4] = {(tid + 0) >> 3, (tid + 256) >> 3,
                         (tid + 512) >> 3, (tid + 768) >> 3};
    const int ac4 = tid & 7;
    const int brow[2] = {(tid + 0) >> 3, (tid + 256) >> 3};

    auto load_global = [&](int k0) {
#pragma unroll
        for (int l = 0; l < 4; l++)
            pa[l] = *(const float4*)&A[(size_t)(bm + arow[l]) * K + k0 + ac4 * 4];
#pragma unroll
        for (int l = 0; l < 2; l++)
            pb[l] = *(const float4*)&B[(size_t)(bn + brow[l]) * K + k0 + ac4 * 4];
    };
    auto store_smem = [&](int buf) {
#pragma unroll
        for (int l = 0; l < 4; l++) {
            uint32_t* d = &As[buf * 128 + arow[l]][ac4 * 4];
            d[0] = f2tf32(pa[l].x); d[1] = f2tf32(pa[l].y);
            d[2] = f2tf32(pa[l].z); d[3] = f2tf32(pa[l].w);
        }
#pragma unroll
        for (int l = 0; l < 2; l++) {
            uint32_t* d = &Bs[buf * 64 + brow[l]][ac4 * 4];
            d[0] = f2tf32(pb[l].x); d[1] = f2tf32(pb[l].y);
            d[2] = f2tf32(pb[l].z); d[3] = f2tf32(pb[l].w);
        }
    };

    float acc[2][4][4];
#pragma unroll
    for (int mi = 0; mi < 2; mi++)
#pragma unroll
        for (int ni = 0; ni < 4; ni++)
#pragma unroll
            for (int r = 0; r < 4; r++) acc[mi][ni][r] = 0.0f;

    const int nstages = K >> 5;
    load_global(0);
    store_smem(0);
    __syncthreads();

    for (int s = 0; s < nstages; s++) {
        if (s + 1 < nstages) load_global((s + 1) << 5);
        const int buf = s & 1;

#pragma unroll
        for (int ks = 0; ks < 4; ks++) {
            const int kb = ks * 8;
            uint32_t af[2][4];
#pragma unroll
            for (int mi = 0; mi < 2; mi++) {
                const int m = buf * 128 + wm * 32 + mi * 16;
                af[mi][0] = As[m + g][kb + tq];
                af[mi][1] = As[m + 8 + g][kb + tq];
                af[mi][2] = As[m + g][kb + tq + 4];
                af[mi][3] = As[m + 8 + g][kb + tq + 4];
            }
            uint32_t bf[4][2];
#pragma unroll
            for (int ni = 0; ni < 4; ni++) {
                const int n = buf * 64 + wn * 32 + ni * 8;
                bf[ni][0] = Bs[n + g][kb + tq];
                bf[ni][1] = Bs[n + g][kb + tq + 4];
            }
#pragma unroll
            for (int mi = 0; mi < 2; mi++)
#pragma unroll
                for (int ni = 0; ni < 4; ni++)
                    mma_tf32(acc[mi][ni], af[mi], bf[ni]);
        }

        if (s + 1 < nstages) {
            store_smem((s + 1) & 1);
            __syncthreads();
        }
    }

#pragma unroll
    for (int mi = 0; mi < 2; mi++)
#pragma unroll
        for (int ni = 0; ni < 4; ni++) {
            const int row = bm + wm * 32 + mi * 16 + g;
            const int col = bn + wn * 32 + ni * 8 + tq * 2;
            *(float2*)&C[(size_t)row * N + col] =
                make_float2(acc[mi][ni][0], acc[mi][ni][1]);
            *(float2*)&C[(size_t)(row + 8) * N + col] =
                make_float2(acc[mi][ni][2], acc[mi][ni][3]);
        }
}

// ---------------------------------------------------------------------------
// RMSNorm + RoPE (in place, unchanged)
// ---------------------------------------------------------------------------
__global__ __launch_bounds__(256) void norm_rope(float* __restrict__ buf,
                                                 const float* __restrict__ w,
                                                 const float* __restrict__ cosb,
                                                 const float* __restrict__ sinb,
                                                 int nheads) {
    const int t = blockIdx.x;
    const int warp = threadIdx.x >> 5;
    const int lane = threadIdx.x & 31;
    const int h = blockIdx.y * 8 + warp;
    if (h >= nheads) return;

    float* p = buf + (size_t)t * nheads * HD + h * HD;
    float a = p[lane];
    float b = p[lane + 32];

    float ss = a * a + b * b;
#pragma unroll
    for (int o = 16; o; o >>= 1) ss += __shfl_xor_sync(0xffffffffu, ss, o);
    float inv = rsqrtf(ss * (1.0f / HD) + 1e-6f);

    a *= inv * w[lane];
    b *= inv * w[lane + 32];

    float c0 = cosb[t * HD + lane];
    float s0 = sinb[t * HD + lane];
    float c1 = cosb[t * HD + lane + 32];
    float s1 = sinb[t * HD + lane + 32];

    p[lane]      = a * c0 - b * s0;
    p[lane + 32] = b * c1 + a * s1;
}

// ---------------------------------------------------------------------------
// Tensor-core flash attention (tf32). One CTA per (qtile=64, head), 4 warps.
// Warp tile: 16 q-rows x 64 kv-cols. Q fragments register-resident.
// Smem: Qs/Ks[c][d] 64x68, Vs[c][d] 64x68, Ps[row][c] 64x68 (fp32 bits,
// cvt to tf32 at fragment load).
// ---------------------------------------------------------------------------
#define ATP 68
__global__ __launch_bounds__(128) void attn_tc(const float* __restrict__ q,
                                               const float* __restrict__ k,
                                               const float* __restrict__ v,
                                               float* __restrict__ out) {
    extern __shared__ float sm[];
    float* Ks = sm;               // [64][ATP]  (stages Q first, then K tiles)
    float* Vs = sm + 64 * ATP;    // [64][ATP]  Vs[c][d]
    float* Ps = sm + 2 * 64 * ATP;

    const int qt = blockIdx.x;
    const int h  = blockIdx.y;
    const int kvh = h >> 2;
    const int tid = threadIdx.x;
    const int lane = tid & 31;
    const int warp = tid >> 5;
    const int g = lane >> 2;
    const int tq = lane & 3;
    const int wr = warp * 16;
    const int row0 = wr + g;
    const int row1 = wr + 8 + g;

    // Stage Q tile into Ks, then build register-resident A fragments.
#pragma unroll
    for (int l = 0; l < 8; l++) {
        int idx = tid + l * 128;
        int r = idx >> 4;
        int c4 = idx & 15;
        float4 qv = *(const float4*)&q[(size_t)(qt * 64 + r) * (NH * HD) +
                                       h * HD + c4 * 4];
        float* d = &Ks[r * ATP + c4 * 4];
        d[0] = qv.x; d[1] = qv.y; d[2] = qv.z; d[3] = qv.w;
    }
    __syncthreads();

    uint32_t qf[8][4];
#pragma unroll
    for (int ks = 0; ks < 8; ks++) {
        qf[ks][0] = f2tf32(Ks[row0 * ATP + ks * 8 + tq]);
        qf[ks][1] = f2tf32(Ks[row1 * ATP + ks * 8 + tq]);
        qf[ks][2] = f2tf32(Ks[row0 * ATP + ks * 8 + tq + 4]);
        qf[ks][3] = f2tf32(Ks[row1 * ATP + ks * 8 + tq + 4]);
    }

    float m0 = -1e30f, m1 = -1e30f, l0 = 0.0f, l1 = 0.0f;
    float oacc[8][4];
#pragma unroll
    for (int nt = 0; nt < 8; nt++)
#pragma unroll
        for (int r = 0; r < 4; r++) oacc[nt][r] = 0.0f;

    for (int s = 0; s <= qt; s++) {
        __syncthreads();  // everyone done with prev K/V (and Q frags built)
#pragma unroll
        for (int l = 0; l < 8; l++) {
            int idx = tid + l * 128;
            int c = idx >> 4;
            int d4 = idx & 15;
            size_t gk = (size_t)(s * 64 + c) * (NKV * HD) + kvh * HD + d4 * 4;
            float4 kv4 = *(const float4*)&k[gk];
            float4 vv4 = *(const float4*)&v[gk];
            float* dk = &Ks[c * ATP + d4 * 4];
            dk[0] = kv4.x; dk[1] = kv4.y; dk[2] = kv4.z; dk[3] = kv4.w;
            float* dv = &Vs[c * ATP + d4 * 4];
            dv[0] = vv4.x; dv[1] = vv4.y; dv[2] = vv4.z; dv[3] = vv4.w;
        }
        __syncthreads();

        // S = Q K^T : per warp 16x64, B frags from Ks (n=c, k=d)
        float sa[8][4];
#pragma unroll
        for (int nt = 0; nt < 8; nt++) {
#pragma unroll
            for (int r = 0; r < 4; r++) sa[nt][r] = 0.0f;
#pragma unroll
            for (int ks = 0; ks < 8; ks++) {
                uint32_t bf[2];
                bf[0] = f2tf32(Ks[(nt * 8 + g) * ATP + ks * 8 + tq]);
                bf[1] = f2tf32(Ks[(nt * 8 + g) * ATP + ks * 8 + tq + 4]);
                mma_tf32(sa[nt], qf[ks], bf);
            }
        }

        // scale + causal mask + online softmax (rows row0, row1)
        const bool diag = (s == qt);
        float rm0 = -1e30f, rm1 = -1e30f;
#pragma unroll
        for (int nt = 0; nt < 8; nt++) {
            int c0i = nt * 8 + 2 * tq;
#pragma unroll
            for (int j = 0; j < 2; j++) {
                float v0 = sa[nt][j] * 0.125f;
                float v1 = sa[nt][2 + j] * 0.125f;
                if (diag && (c0i + j > row0)) v0 = -1e30f;
                if (diag && (c0i + j > row1)) v1 = -1e30f;
                sa[nt][j] = v0;
                sa[nt][2 + j] = v1;
                rm0 = fmaxf(rm0, v0);
                rm1 = fmaxf(rm1, v1);
            }
        }
#pragma unroll
        for (int o = 1; o < 4; o <<= 1) {
            rm0 = fmaxf(rm0, __shfl_xor_sync(0xffffffffu, rm0, o));
            rm1 = fmaxf(rm1, __shfl_xor_sync(0xffffffffu, rm1, o));
        }
        float nm0 = fmaxf(m0, rm0), nm1 = fmaxf(m1, rm1);
        float cr0 = __expf(m0 - nm0), cr1 = __expf(m1 - nm1);
        m0 = nm0; m1 = nm1;
        float rs0 = 0.0f, rs1 = 0.0f;
#pragma unroll
        for (int nt = 0; nt < 8; nt++) {
#pragma unroll
            for (int j = 0; j < 2; j++) {
                float p0 = __expf(sa[nt][j] - m0);
                float p1 = __expf(sa[nt][2 + j] - m1);
                sa[nt][j] = p0;
                sa[nt][2 + j] = p1;
                rs0 += p0;
                rs1 += p1;
            }
        }
#pragma unroll
        for (int o = 1; o < 4; o <<= 1) {
            rs0 += __shfl_xor_sync(0xffffffffu, rs0, o);
            rs1 += __shfl_xor_sync(0xffffffffu, rs1, o);
        }
        l0 = l0 * cr0 + rs0;
        l1 = l1 * cr1 + rs1;
#pragma unroll
        for (int nt = 0; nt < 8; nt++) {
            oacc[nt][0] *= cr0; oacc[nt][1] *= cr0;
            oacc[nt][2] *= cr1; oacc[nt][3] *= cr1;
        }

        // P -> per-warp smem slice (rows wr..wr+15 only)
#pragma unroll
        for (int nt = 0; nt < 8; nt++) {
            int c0i = nt * 8 + 2 * tq;
            Ps[row0 * ATP + c0i]     = sa[nt][0];
            Ps[row0 * ATP + c0i + 1] = sa[nt][1];
            Ps[row1 * ATP + c0i]     = sa[nt][2];
            Ps[row1 * ATP + c0i + 1] = sa[nt][3];
        }
        __syncwarp();

        // O += P V : A frags from Ps (m=row, k=c), B from Vs (n=d, k=c)
#pragma unroll
        for (int ks = 0; ks < 8; ks++) {
            uint32_t af[4];
            af[0] = f2tf32(Ps[row0 * ATP + ks * 8 + tq]);
            af[1] = f2tf32(Ps[row1 * ATP + ks * 8 + tq]);
            af[2] = f2tf32(Ps[row0 * ATP + ks * 8 + tq + 4]);
            af[3] = f2tf32(Ps[row1 * ATP + ks * 8 + tq + 4]);
#pragma unroll
            for (int nt = 0; nt < 8; nt++) {
                uint32_t bf[2];
                bf[0] = f2tf32(Vs[(ks * 8 + tq) * ATP + nt * 8 + g]);
                bf[1] = f2tf32(Vs[(ks * 8 + tq + 4) * ATP + nt * 8 + g]);
                mma_tf32(oacc[nt], af, bf);
            }
        }
    }

    // Epilogue
    float inv0 = 1.0f / l0, inv1 = 1.0f / l1;
#pragma unroll
    for (int nt = 0; nt < 8; nt++) {
        int col = h * HD + nt * 8 + 2 * tq;
        *(float2*)&out[(size_t)(qt * 64 + row0) * (NH * HD) + col] =
            make_float2(oacc[nt][0] * inv0, oacc[nt][1] * inv0);
        *(float2*)&out[(size_t)(qt * 64 + row1) * (NH * HD) + col] =
            make_float2(oacc[nt][2] * inv1, oacc[nt][3] * inv1);
    }
}

// ---------------------------------------------------------------------------
// Inputs: 0=x 1=scale_x 2=mask 3=cos 4=scale_cos 5=sin 6=scale_sin
//         7=Wq 8=Wk 9=Wv 10=Wo 11=q_norm_w 12=k_norm_w
// ---------------------------------------------------------------------------
extern "C" void kernel_launch(void* const* d_in, const int* in_sizes, int n_in,
                              void* d_out, int out_size) {
    const float* x    = (const float*)d_in[0];
    const float* cosb = (const float*)d_in[3];
    const float* sinb = (const float*)d_in[5];
    const float* Wq   = (const float*)d_in[7];
    const float* Wk   = (const float*)d_in[8];
    const float* Wv   = (const float*)d_in[9];
    const float* Wo   = (const float*)d_in[10];
    const float* qw   = (const float*)d_in[11];
    const float* kw   = (const float*)d_in[12];
    float* out = (float*)d_out;

    float *qb, *kb, *vb, *ab;
    cudaGetSymbolAddress((void**)&qb, g_q);
    cudaGetSymbolAddress((void**)&kb, g_k);
    cudaGetSymbolAddress((void**)&vb, g_v);
    cudaGetSymbolAddress((void**)&ab, g_att);

    const int gsmem = (2 * 128 * 36 + 2 * 64 * 36) * (int)sizeof(uint32_t);
    cudaFuncSetAttribute(gemm_tf32,
                         cudaFuncAttributeMaxDynamicSharedMemorySize, gsmem);
    const int asmem = 3 * 64 * ATP * (int)sizeof(float);
    cudaFuncSetAttribute(attn_tc,
                         cudaFuncAttributeMaxDynamicSharedMemorySize, asmem);

    // QKV projections (tf32 tensor cores, double-buffered)
    gemm_tf32<<<dim3(32, 8), 256, gsmem>>>(x, Wq, qb, T_TOK, NH * HD, DIN);
    gemm_tf32<<<dim3(8, 8), 256, gsmem>>>(x, Wk, kb, T_TOK, NKV * HD, DIN);
    gemm_tf32<<<dim3(8, 8), 256, gsmem>>>(x, Wv, vb, T_TOK, NKV * HD, DIN);

    // RMSNorm + RoPE (in place)
    norm_rope<<<dim3(T_TOK, 4), 256>>>(qb, qw, cosb, sinb, NH);
    norm_rope<<<dim3(T_TOK, 1), 256>>>(kb, kw, cosb, sinb, NKV);

    // Causal GQA attention (tf32 tensor cores)
    attn_tc<<<dim3(16, 32), 128, asmem>>>(qb, kb, vb, ab);

    // Output projection
    gemm_tf32<<<dim3(32, 8), 256, gsmem>>>(ab, Wo, out, T_TOK, DIN, NH * HD);
}

// round 5
// speedup vs baseline: 3.9867x; 1.4840x over previous
#include <cuda_runtime.h>
#include <cuda_fp16.h>
#include <stdint.h>
#include <math.h>

#define T_TOK 1024
#define DIN   2048
#define NH    32
#define NKV   8
#define HD    64

__device__ float g_q[T_TOK * NH * HD];
__device__ float g_k[T_TOK * NKV * HD];
__device__ float g_v[T_TOK * NKV * HD];
__device__ float g_att[T_TOK * NH * HD];

// ---------------------------------------------------------------------------
// mma helpers
// ---------------------------------------------------------------------------
__device__ __forceinline__ uint32_t f2tf32(float f) {
    uint32_t r;
    asm("cvt.rna.tf32.f32 %0, %1;" : "=r"(r) : "f"(f));
    return r;
}

__device__ __forceinline__ void mma_tf32(float* c, const uint32_t* a,
                                         const uint32_t* b) {
    asm volatile(
        "mma.sync.aligned.m16n8k8.row.col.f32.tf32.tf32.f32 "
        "{%0,%1,%2,%3},{%4,%5,%6,%7},{%8,%9},{%0,%1,%2,%3};"
        : "+f"(c[0]), "+f"(c[1]), "+f"(c[2]), "+f"(c[3])
        : "r"(a[0]), "r"(a[1]), "r"(a[2]), "r"(a[3]), "r"(b[0]), "r"(b[1]));
}

__device__ __forceinline__ void mma_f16(float* c, const uint32_t* a,
                                        const uint32_t* b) {
    asm volatile(
        "mma.sync.aligned.m16n8k16.row.col.f32.f16.f16.f32 "
        "{%0,%1,%2,%3},{%4,%5,%6,%7},{%8,%9},{%0,%1,%2,%3};"
        : "+f"(c[0]), "+f"(c[1]), "+f"(c[2]), "+f"(c[3])
        : "r"(a[0]), "r"(a[1]), "r"(a[2]), "r"(a[3]), "r"(b[0]), "r"(b[1]));
}

// ---------------------------------------------------------------------------
// fp16 GEMM: C[M,N] = A[M,K] * B[N,K]^T  (A,B fp32 in gmem, fp16 in smem).
// 128x128 block tile, 512 threads (16 warps 4x4), warp tile 32x32,
// K-chunk 32 double-buffered. Smem pitch 40 halves (conflict-free frags).
// ---------------------------------------------------------------------------
#define GP 40
__device__ __forceinline__ void gemm_tile_f16(const float* __restrict__ A,
                                              const float* __restrict__ B,
                                              float* __restrict__ C,
                                              int N, int K, int bm, int bn,
                                              __half* sa_base) {
    __half* sb_base = sa_base + 2 * 128 * GP;   // A: 2 bufs, then B: 2 bufs

    const int tid  = threadIdx.x;
    const int lane = tid & 31;
    const int warp = tid >> 5;
    const int g    = lane >> 2;
    const int tq   = lane & 3;
    const int wm   = warp & 3;    // 0..3 -> m = wm*32
    const int wn   = warp >> 2;   // 0..3 -> n = wn*32

    float4 pa[2], pb[2];
    const int row0 = (tid + 0) >> 3;       // 0..63
    const int row1 = (tid + 512) >> 3;     // 64..127
    const int c4   = tid & 7;

    auto load_global = [&](int k0) {
        pa[0] = *(const float4*)&A[(size_t)(bm + row0) * K + k0 + c4 * 4];
        pa[1] = *(const float4*)&A[(size_t)(bm + row1) * K + k0 + c4 * 4];
        pb[0] = *(const float4*)&B[(size_t)(bn + row0) * K + k0 + c4 * 4];
        pb[1] = *(const float4*)&B[(size_t)(bn + row1) * K + k0 + c4 * 4];
    };
    auto store_smem = [&](int buf) {
        __half* sa = sa_base + buf * 128 * GP;
        __half* sb = sb_base + buf * 128 * GP;
        {
            __half2 lo = __floats2half2_rn(pa[0].x, pa[0].y);
            __half2 hi = __floats2half2_rn(pa[0].z, pa[0].w);
            *(__half2*)&sa[row0 * GP + c4 * 4]     = lo;
            *(__half2*)&sa[row0 * GP + c4 * 4 + 2] = hi;
            lo = __floats2half2_rn(pa[1].x, pa[1].y);
            hi = __floats2half2_rn(pa[1].z, pa[1].w);
            *(__half2*)&sa[row1 * GP + c4 * 4]     = lo;
            *(__half2*)&sa[row1 * GP + c4 * 4 + 2] = hi;
        }
        {
            __half2 lo = __floats2half2_rn(pb[0].x, pb[0].y);
            __half2 hi = __floats2half2_rn(pb[0].z, pb[0].w);
            *(__half2*)&sb[row0 * GP + c4 * 4]     = lo;
            *(__half2*)&sb[row0 * GP + c4 * 4 + 2] = hi;
            lo = __floats2half2_rn(pb[1].x, pb[1].y);
            hi = __floats2half2_rn(pb[1].z, pb[1].w);
            *(__half2*)&sb[row1 * GP + c4 * 4]     = lo;
            *(__half2*)&sb[row1 * GP + c4 * 4 + 2] = hi;
        }
    };

    float acc[2][4][4];
#pragma unroll
    for (int mi = 0; mi < 2; mi++)
#pragma unroll
        for (int ni = 0; ni < 4; ni++)
#pragma unroll
            for (int r = 0; r < 4; r++) acc[mi][ni][r] = 0.0f;

    const int nch = K >> 5;
    load_global(0);
    store_smem(0);
    __syncthreads();

    for (int c = 0; c < nch; c++) {
        if (c + 1 < nch) load_global((c + 1) << 5);
        const int buf = c & 1;
        const __half* sa = sa_base + buf * 128 * GP;
        const __half* sb = sb_base + buf * 128 * GP;

#pragma unroll
        for (int ks = 0; ks < 2; ks++) {
            const int k0 = ks * 16;
            uint32_t af[2][4];
#pragma unroll
            for (int mi = 0; mi < 2; mi++) {
                const int m = wm * 32 + mi * 16;
                af[mi][0] = *(const uint32_t*)&sa[(m + g) * GP + k0 + 2 * tq];
                af[mi][1] = *(const uint32_t*)&sa[(m + 8 + g) * GP + k0 + 2 * tq];
                af[mi][2] = *(const uint32_t*)&sa[(m + g) * GP + k0 + 8 + 2 * tq];
                af[mi][3] = *(const uint32_t*)&sa[(m + 8 + g) * GP + k0 + 8 + 2 * tq];
            }
            uint32_t bf[4][2];
#pragma unroll
            for (int ni = 0; ni < 4; ni++) {
                const int n = wn * 32 + ni * 8;
                bf[ni][0] = *(const uint32_t*)&sb[(n + g) * GP + k0 + 2 * tq];
                bf[ni][1] = *(const uint32_t*)&sb[(n + g) * GP + k0 + 8 + 2 * tq];
            }
#pragma unroll
            for (int mi = 0; mi < 2; mi++)
#pragma unroll
                for (int ni = 0; ni < 4; ni++)
                    mma_f16(acc[mi][ni], af[mi], bf[ni]);
        }

        if (c + 1 < nch) {
            store_smem(buf ^ 1);
            __syncthreads();
        }
    }

#pragma unroll
    for (int mi = 0; mi < 2; mi++)
#pragma unroll
        for (int ni = 0; ni < 4; ni++) {
            const int row = bm + wm * 32 + mi * 16 + g;
            const int col = bn + wn * 32 + ni * 8 + tq * 2;
            *(float2*)&C[(size_t)row * N + col] =
                make_float2(acc[mi][ni][0], acc[mi][ni][1]);
            *(float2*)&C[(size_t)(row + 8) * N + col] =
                make_float2(acc[mi][ni][2], acc[mi][ni][3]);
        }
}

__global__ __launch_bounds__(512) void gemm_f16(const float* __restrict__ A,
                                                const float* __restrict__ B,
                                                float* __restrict__ C,
                                                int N, int K) {
    extern __shared__ __half sh[];
    gemm_tile_f16(A, B, C, N, K, blockIdx.y * 128, blockIdx.x * 128, sh);
}

// Fused QKV: bx<16 -> Wq, bx<20 -> Wk, else Wv
__global__ __launch_bounds__(512) void gemm_qkv_f16(
    const float* __restrict__ x,
    const float* __restrict__ Wq, const float* __restrict__ Wk,
    const float* __restrict__ Wv,
    float* __restrict__ qb, float* __restrict__ kb, float* __restrict__ vb) {
    extern __shared__ __half sh[];
    const int bx = blockIdx.x;
    const float* B;
    float* C;
    int N, bn;
    if (bx < 16)      { B = Wq; C = qb; N = 2048; bn = bx * 128; }
    else if (bx < 20) { B = Wk; C = kb; N = 512;  bn = (bx - 16) * 128; }
    else              { B = Wv; C = vb; N = 512;  bn = (bx - 20) * 128; }
    gemm_tile_f16(x, B, C, N, 2048, blockIdx.y * 128, bn, sh);
}

// ---------------------------------------------------------------------------
// RMSNorm + RoPE, q and k in one launch: blockIdx.y<4 -> q heads, ==4 -> k.
// ---------------------------------------------------------------------------
__global__ __launch_bounds__(256) void norm_rope2(float* __restrict__ qb,
                                                  float* __restrict__ kb,
                                                  const float* __restrict__ qw,
                                                  const float* __restrict__ kw,
                                                  const float* __restrict__ cosb,
                                                  const float* __restrict__ sinb) {
    const int t = blockIdx.x;
    const int warp = threadIdx.x >> 5;
    const int lane = threadIdx.x & 31;
    const bool isk = (blockIdx.y == 4);
    const int h = isk ? warp : blockIdx.y * 8 + warp;
    const int nheads = isk ? NKV : NH;
    const float* w = isk ? kw : qw;
    float* buf = isk ? kb : qb;

    float* p = buf + (size_t)t * nheads * HD + h * HD;
    float a = p[lane];
    float b = p[lane + 32];

    float ss = a * a + b * b;
#pragma unroll
    for (int o = 16; o; o >>= 1) ss += __shfl_xor_sync(0xffffffffu, ss, o);
    float inv = rsqrtf(ss * (1.0f / HD) + 1e-6f);

    a *= inv * w[lane];
    b *= inv * w[lane + 32];

    float c0 = cosb[t * HD + lane];
    float s0 = sinb[t * HD + lane];
    float c1 = cosb[t * HD + lane + 32];
    float s1 = sinb[t * HD + lane + 32];

    p[lane]      = a * c0 - b * s0;
    p[lane + 32] = b * c1 + a * s1;
}

// ---------------------------------------------------------------------------
// Tensor-core flash attention (tf32 legacy mma) — unchanged from R3.
// ---------------------------------------------------------------------------
#define ATP 68
__global__ __launch_bounds__(128) void attn_tc(const float* __restrict__ q,
                                               const float* __restrict__ k,
                                               const float* __restrict__ v,
                                               float* __restrict__ out) {
    extern __shared__ float sm[];
    float* Ks = sm;
    float* Vs = sm + 64 * ATP;
    float* Ps = sm + 2 * 64 * ATP;

    const int qt = blockIdx.x;
    const int h  = blockIdx.y;
    const int kvh = h >> 2;
    const int tid = threadIdx.x;
    const int lane = tid & 31;
    const int warp = tid >> 5;
    const int g = lane >> 2;
    const int tq = lane & 3;
    const int wr = warp * 16;
    const int row0 = wr + g;
    const int row1 = wr + 8 + g;

#pragma unroll
    for (int l = 0; l < 8; l++) {
        int idx = tid + l * 128;
        int r = idx >> 4;
        int c4 = idx & 15;
        float4 qv = *(const float4*)&q[(size_t)(qt * 64 + r) * (NH * HD) +
                                       h * HD + c4 * 4];
        float* d = &Ks[r * ATP + c4 * 4];
        d[0] = qv.x; d[1] = qv.y; d[2] = qv.z; d[3] = qv.w;
    }
    __syncthreads();

    uint32_t qf[8][4];
#pragma unroll
    for (int ks = 0; ks < 8; ks++) {
        qf[ks][0] = f2tf32(Ks[row0 * ATP + ks * 8 + tq]);
        qf[ks][1] = f2tf32(Ks[row1 * ATP + ks * 8 + tq]);
        qf[ks][2] = f2tf32(Ks[row0 * ATP + ks * 8 + tq + 4]);
        qf[ks][3] = f2tf32(Ks[row1 * ATP + ks * 8 + tq + 4]);
    }

    float m0 = -1e30f, m1 = -1e30f, l0 = 0.0f, l1 = 0.0f;
    float oacc[8][4];
#pragma unroll
    for (int nt = 0; nt < 8; nt++)
#pragma unroll
        for (int r = 0; r < 4; r++) oacc[nt][r] = 0.0f;

    for (int s = 0; s <= qt; s++) {
        __syncthreads();
#pragma unroll
        for (int l = 0; l < 8; l++) {
            int idx = tid + l * 128;
            int c = idx >> 4;
            int d4 = idx & 15;
            size_t gk = (size_t)(s * 64 + c) * (NKV * HD) + kvh * HD + d4 * 4;
            float4 kv4 = *(const float4*)&k[gk];
            float4 vv4 = *(const float4*)&v[gk];
            float* dk = &Ks[c * ATP + d4 * 4];
            dk[0] = kv4.x; dk[1] = kv4.y; dk[2] = kv4.z; dk[3] = kv4.w;
            float* dv = &Vs[c * ATP + d4 * 4];
            dv[0] = vv4.x; dv[1] = vv4.y; dv[2] = vv4.z; dv[3] = vv4.w;
        }
        __syncthreads();

        float sa[8][4];
#pragma unroll
        for (int nt = 0; nt < 8; nt++) {
#pragma unroll
            for (int r = 0; r < 4; r++) sa[nt][r] = 0.0f;
#pragma unroll
            for (int ks = 0; ks < 8; ks++) {
                uint32_t bf[2];
                bf[0] = f2tf32(Ks[(nt * 8 + g) * ATP + ks * 8 + tq]);
                bf[1] = f2tf32(Ks[(nt * 8 + g) * ATP + ks * 8 + tq + 4]);
                mma_tf32(sa[nt], qf[ks], bf);
            }
        }

        const bool diag = (s == qt);
        float rm0 = -1e30f, rm1 = -1e30f;
#pragma unroll
        for (int nt = 0; nt < 8; nt++) {
            int c0i = nt * 8 + 2 * tq;
#pragma unroll
            for (int j = 0; j < 2; j++) {
                float v0 = sa[nt][j] * 0.125f;
                float v1 = sa[nt][2 + j] * 0.125f;
                if (diag && (c0i + j > row0)) v0 = -1e30f;
                if (diag && (c0i + j > row1)) v1 = -1e30f;
                sa[nt][j] = v0;
                sa[nt][2 + j] = v1;
                rm0 = fmaxf(rm0, v0);
                rm1 = fmaxf(rm1, v1);
            }
        }
#pragma unroll
        for (int o = 1; o < 4; o <<= 1) {
            rm0 = fmaxf(rm0, __shfl_xor_sync(0xffffffffu, rm0, o));
            rm1 = fmaxf(rm1, __shfl_xor_sync(0xffffffffu, rm1, o));
        }
        float nm0 = fmaxf(m0, rm0), nm1 = fmaxf(m1, rm1);
        float cr0 = __expf(m0 - nm0), cr1 = __expf(m1 - nm1);
        m0 = nm0; m1 = nm1;
        float rs0 = 0.0f, rs1 = 0.0f;
#pragma unroll
        for (int nt = 0; nt < 8; nt++) {
#pragma unroll
            for (int j = 0; j < 2; j++) {
                float p0 = __expf(sa[nt][j] - m0);
                float p1 = __expf(sa[nt][2 + j] - m1);
                sa[nt][j] = p0;
                sa[nt][2 + j] = p1;
                rs0 += p0;
                rs1 += p1;
            }
        }
#pragma unroll
        for (int o = 1; o < 4; o <<= 1) {
            rs0 += __shfl_xor_sync(0xffffffffu, rs0, o);
            rs1 += __shfl_xor_sync(0xffffffffu, rs1, o);
        }
        l0 = l0 * cr0 + rs0;
        l1 = l1 * cr1 + rs1;
#pragma unroll
        for (int nt = 0; nt < 8; nt++) {
            oacc[nt][0] *= cr0; oacc[nt][1] *= cr0;
            oacc[nt][2] *= cr1; oacc[nt][3] *= cr1;
        }

#pragma unroll
        for (int nt = 0; nt < 8; nt++) {
            int c0i = nt * 8 + 2 * tq;
            Ps[row0 * ATP + c0i]     = sa[nt][0];
            Ps[row0 * ATP + c0i + 1] = sa[nt][1];
            Ps[row1 * ATP + c0i]     = sa[nt][2];
            Ps[row1 * ATP + c0i + 1] = sa[nt][3];
        }
        __syncwarp();

#pragma unroll
        for (int ks = 0; ks < 8; ks++) {
            uint32_t af[4];
            af[0] = f2tf32(Ps[row0 * ATP + ks * 8 + tq]);
            af[1] = f2tf32(Ps[row1 * ATP + ks * 8 + tq]);
            af[2] = f2tf32(Ps[row0 * ATP + ks * 8 + tq + 4]);
            af[3] = f2tf32(Ps[row1 * ATP + ks * 8 + tq + 4]);
#pragma unroll
            for (int nt = 0; nt < 8; nt++) {
                uint32_t bf[2];
                bf[0] = f2tf32(Vs[(ks * 8 + tq) * ATP + nt * 8 + g]);
                bf[1] = f2tf32(Vs[(ks * 8 + tq + 4) * ATP + nt * 8 + g]);
                mma_tf32(oacc[nt], af, bf);
            }
        }
    }

    float inv0 = 1.0f / l0, inv1 = 1.0f / l1;
#pragma unroll
    for (int nt = 0; nt < 8; nt++) {
        int col = h * HD + nt * 8 + 2 * tq;
        *(float2*)&out[(size_t)(qt * 64 + row0) * (NH * HD) + col] =
            make_float2(oacc[nt][0] * inv0, oacc[nt][1] * inv0);
        *(float2*)&out[(size_t)(qt * 64 + row1) * (NH * HD) + col] =
            make_float2(oacc[nt][2] * inv1, oacc[nt][3] * inv1);
    }
}

// ---------------------------------------------------------------------------
// Inputs: 0=x 1=scale_x 2=mask 3=cos 4=scale_cos 5=sin 6=scale_sin
//         7=Wq 8=Wk 9=Wv 10=Wo 11=q_norm_w 12=k_norm_w
// ---------------------------------------------------------------------------
extern "C" void kernel_launch(void* const* d_in, const int* in_sizes, int n_in,
                              void* d_out, int out_size) {
    const float* x    = (const float*)d_in[0];
    const float* cosb = (const float*)d_in[3];
    const float* sinb = (const float*)d_in[5];
    const float* Wq   = (const float*)d_in[7];
    const float* Wk   = (const float*)d_in[8];
    const float* Wv   = (const float*)d_in[9];
    const float* Wo   = (const float*)d_in[10];
    const float* qw   = (const float*)d_in[11];
    const float* kw   = (const float*)d_in[12];
    float* out = (float*)d_out;

    float *qb, *kb, *vb, *ab;
    cudaGetSymbolAddress((void**)&qb, g_q);
    cudaGetSymbolAddress((void**)&kb, g_k);
    cudaGetSymbolAddress((void**)&vb, g_v);
    cudaGetSymbolAddress((void**)&ab, g_att);

    const int gsmem = 4 * 128 * GP * (int)sizeof(__half);  // 40960 B
    cudaFuncSetAttribute(gemm_qkv_f16,
                         cudaFuncAttributeMaxDynamicSharedMemorySize, gsmem);
    cudaFuncSetAttribute(gemm_f16,
                         cudaFuncAttributeMaxDynamicSharedMemorySize, gsmem);
    const int asmem = 3 * 64 * ATP * (int)sizeof(float);
    cudaFuncSetAttribute(attn_tc,
                         cudaFuncAttributeMaxDynamicSharedMemorySize, asmem);

    // Fused QKV projection (fp16 tensor cores)
    gemm_qkv_f16<<<dim3(24, 8), 512, gsmem>>>(x, Wq, Wk, Wv, qb, kb, vb);

    // RMSNorm + RoPE (q + k in one launch)
    norm_rope2<<<dim3(T_TOK, 5), 256>>>(qb, kb, qw, kw, cosb, sinb);

    // Causal GQA attention (tf32 legacy mma)
    attn_tc<<<dim3(16, 32), 128, asmem>>>(qb, kb, vb, ab);

    // Output projection (fp16 tensor cores)
    gemm_f16<<<dim3(16, 8), 512, gsmem>>>(ab, Wo, out, DIN, NH * HD);
}

// round 6
// speedup vs baseline: 6.1757x; 1.5491x over previous
#include <cuda_runtime.h>
#include <cuda_fp16.h>
#include <stdint.h>
#include <math.h>

#define T_TOK 1024
#define DIN   2048
#define NH    32
#define NKV   8
#define HD    64

__device__ float g_q[T_TOK * NH * HD];
__device__ float g_k[T_TOK * NKV * HD];
__device__ float g_v[T_TOK * NKV * HD];
__device__ __half g_xh[T_TOK * DIN];
__device__ __half g_wqh[NH * HD * DIN];
__device__ __half g_wkh[NKV * HD * DIN];
__device__ __half g_wvh[NKV * HD * DIN];
__device__ __half g_woh[DIN * NH * HD];
__device__ __half g_abh[T_TOK * NH * HD];

// ---------------------------------------------------------------------------
// asm helpers
// ---------------------------------------------------------------------------
__device__ __forceinline__ uint32_t f2tf32(float f) {
    uint32_t r;
    asm("cvt.rna.tf32.f32 %0, %1;" : "=r"(r) : "f"(f));
    return r;
}

__device__ __forceinline__ uint32_t smem_u32(const void* p) {
    uint32_t a;
    asm("{ .reg .u64 t; cvta.to.shared.u64 t, %1; cvt.u32.u64 %0, t; }"
        : "=r"(a) : "l"(p));
    return a;
}

__device__ __forceinline__ void mma_tf32(float* c, const uint32_t* a,
                                         const uint32_t* b) {
    asm volatile(
        "mma.sync.aligned.m16n8k8.row.col.f32.tf32.tf32.f32 "
        "{%0,%1,%2,%3},{%4,%5,%6,%7},{%8,%9},{%0,%1,%2,%3};"
        : "+f"(c[0]), "+f"(c[1]), "+f"(c[2]), "+f"(c[3])
        : "r"(a[0]), "r"(a[1]), "r"(a[2]), "r"(a[3]), "r"(b[0]), "r"(b[1]));
}

__device__ __forceinline__ void mma_f16(float* c, const uint32_t* a,
                                        const uint32_t* b) {
    asm volatile(
        "mma.sync.aligned.m16n8k16.row.col.f32.f16.f16.f32 "
        "{%0,%1,%2,%3},{%4,%5,%6,%7},{%8,%9},{%0,%1,%2,%3};"
        : "+f"(c[0]), "+f"(c[1]), "+f"(c[2]), "+f"(c[3])
        : "r"(a[0]), "r"(a[1]), "r"(a[2]), "r"(a[3]), "r"(b[0]), "r"(b[1]));
}

__device__ __forceinline__ void ldsm_x4(uint32_t* r, uint32_t addr) {
    asm volatile(
        "ldmatrix.sync.aligned.m8n8.x4.shared.b16 {%0,%1,%2,%3}, [%4];"
        : "=r"(r[0]), "=r"(r[1]), "=r"(r[2]), "=r"(r[3]) : "r"(addr));
}

__device__ __forceinline__ void cp16(uint32_t d, const void* s) {
    asm volatile("cp.async.cg.shared.global [%0], [%1], 16;"
                 :: "r"(d), "l"(s));
}
__device__ __forceinline__ void cp_commit() {
    asm volatile("cp.async.commit_group;");
}
template <int N>
__device__ __forceinline__ void cp_wait() {
    asm volatile("cp.async.wait_group %0;" :: "n"(N));
}

#define SW128(o) ((o) ^ (((o) >> 3) & 0x70))

// ---------------------------------------------------------------------------
// Convert fp32 inputs to fp16 scratch (x, Wq, Wk, Wv, Wo). 12M elems, 4/thread.
// ---------------------------------------------------------------------------
#define CE_X  (T_TOK * DIN)              // 2M
#define CE_WQ (NH * HD * DIN)            // 4M
#define CE_WK (NKV * HD * DIN)           // 1M
#define CE_TOT (CE_X + CE_WQ + 3 * CE_WK + CE_WQ)  // not used; explicit below

__global__ __launch_bounds__(256) void cvt_all(const float* __restrict__ x,
                                               const float* __restrict__ Wq,
                                               const float* __restrict__ Wk,
                                               const float* __restrict__ Wv,
                                               const float* __restrict__ Wo) {
    const size_t e = ((size_t)blockIdx.x * 256 + threadIdx.x) * 4;
    const float* src;
    __half* dst;
    size_t base;
    if (e < 2097152)        { src = x;  dst = g_xh;  base = 0; }
    else if (e < 6291456)   { src = Wq; dst = g_wqh; base = 2097152; }
    else if (e < 7340032)   { src = Wk; dst = g_wkh; base = 6291456; }
    else if (e < 8388608)   { src = Wv; dst = g_wvh; base = 7340032; }
    else                    { src = Wo; dst = g_woh; base = 8388608; }
    const size_t o = e - base;
    float4 v = *(const float4*)&src[o];
    *(__half2*)&dst[o]     = __floats2half2_rn(v.x, v.y);
    *(__half2*)&dst[o + 2] = __floats2half2_rn(v.z, v.w);
}

// ---------------------------------------------------------------------------
// fp16 GEMM via cp.async + ldmatrix. C[M,N]=A[M,K]*B[N,K]^T, A/B fp16, C fp32.
// CTA tile 128x128, 256 thr (8 warps 2x4), warp tile 64x32.
// K-chunk 64 halves (128B rows, SW128), 2-stage cp.async pipeline.
// ---------------------------------------------------------------------------
__device__ __forceinline__ void gemm_tile_h(const __half* __restrict__ A,
                                            const __half* __restrict__ B,
                                            float* __restrict__ C,
                                            int N, int K, int bm, int bn,
                                            char* smem) {
    const uint32_t sbase = smem_u32(smem);
    const int tid  = threadIdx.x;
    const int lane = tid & 31;
    const int warp = tid >> 5;
    const int g    = lane >> 2;
    const int tq   = lane & 3;
    const int wm   = warp & 1;    // m group of 64
    const int wn   = warp >> 1;   // n group of 32
    const int quad = lane >> 3;
    const int lr   = lane & 7;
    const int ldrow = tid >> 3;
    const int ldc16 = tid & 7;

    auto stage = [&](int k0, int buf) {
        uint32_t dA = sbase + buf * 32768;
        uint32_t dB = dA + 16384;
#pragma unroll
        for (int p = 0; p < 4; p++) {
            int r = ldrow + p * 32;
            cp16(dA + SW128(r * 128 + ldc16 * 16),
                 &A[(size_t)(bm + r) * K + k0 + ldc16 * 8]);
            cp16(dB + SW128(r * 128 + ldc16 * 16),
                 &B[(size_t)(bn + r) * K + k0 + ldc16 * 8]);
        }
    };

    float acc[4][4][4];
#pragma unroll
    for (int mi = 0; mi < 4; mi++)
#pragma unroll
        for (int ni = 0; ni < 4; ni++)
#pragma unroll
            for (int r = 0; r < 4; r++) acc[mi][ni][r] = 0.0f;

    stage(0, 0);
    cp_commit();
    stage(64, 1);
    cp_commit();

    const int nch = K >> 6;
    for (int c = 0; c < nch; c++) {
        if (c == nch - 1) cp_wait<0>(); else cp_wait<1>();
        __syncthreads();
        const uint32_t sA = sbase + (c & 1) * 32768;
        const uint32_t sB = sA + 16384;

#pragma unroll
        for (int ks = 0; ks < 4; ks++) {
            uint32_t af[4][4];
#pragma unroll
            for (int mi = 0; mi < 4; mi++) {
                int row = wm * 64 + mi * 16 + (quad & 1) * 8 + lr;
                int colb = ks * 32 + (quad >> 1) * 16;
                ldsm_x4(af[mi], sA + SW128(row * 128 + colb));
            }
            uint32_t bf[2][4];
#pragma unroll
            for (int np = 0; np < 2; np++) {
                int row = wn * 32 + np * 16 + (quad >> 1) * 8 + lr;
                int colb = ks * 32 + (quad & 1) * 16;
                ldsm_x4(bf[np], sB + SW128(row * 128 + colb));
            }
#pragma unroll
            for (int mi = 0; mi < 4; mi++)
#pragma unroll
                for (int ni = 0; ni < 4; ni++)
                    mma_f16(acc[mi][ni], af[mi], &bf[ni >> 1][(ni & 1) * 2]);
        }

        if (c + 2 < nch) {
            __syncthreads();
            stage((c + 2) << 6, c & 1);
            cp_commit();
        }
    }

#pragma unroll
    for (int mi = 0; mi < 4; mi++)
#pragma unroll
        for (int ni = 0; ni < 4; ni++) {
            const int row = bm + wm * 64 + mi * 16 + g;
            const int col = bn + wn * 32 + ni * 8 + tq * 2;
            *(float2*)&C[(size_t)row * N + col] =
                make_float2(acc[mi][ni][0], acc[mi][ni][1]);
            *(float2*)&C[(size_t)(row + 8) * N + col] =
                make_float2(acc[mi][ni][2], acc[mi][ni][3]);
        }
}

__global__ __launch_bounds__(256) void gemm_h(const __half* __restrict__ A,
                                              const __half* __restrict__ B,
                                              float* __restrict__ C,
                                              int N, int K) {
    extern __shared__ char sh[];
    gemm_tile_h(A, B, C, N, K, blockIdx.y * 128, blockIdx.x * 128, sh);
}

// Fused QKV: bx<16 -> Wq, bx<20 -> Wk, else Wv
__global__ __launch_bounds__(256) void gemm_qkv_h(float* __restrict__ qb,
                                                  float* __restrict__ kb,
                                                  float* __restrict__ vb) {
    extern __shared__ char sh[];
    const int bx = blockIdx.x;
    const __half* B;
    float* C;
    int N, bn;
    if (bx < 16)      { B = g_wqh; C = qb; N = 2048; bn = bx * 128; }
    else if (bx < 20) { B = g_wkh; C = kb; N = 512;  bn = (bx - 16) * 128; }
    else              { B = g_wvh; C = vb; N = 512;  bn = (bx - 20) * 128; }
    gemm_tile_h(g_xh, B, C, N, 2048, blockIdx.y * 128, bn, sh);
}

// ---------------------------------------------------------------------------
// RMSNorm + RoPE, q and k fused: blockIdx.y<4 -> q heads, ==4 -> k.
// ---------------------------------------------------------------------------
__global__ __launch_bounds__(256) void norm_rope2(float* __restrict__ qb,
                                                  float* __restrict__ kb,
                                                  const float* __restrict__ qw,
                                                  const float* __restrict__ kw,
                                                  const float* __restrict__ cosb,
                                                  const float* __restrict__ sinb) {
    const int t = blockIdx.x;
    const int warp = threadIdx.x >> 5;
    const int lane = threadIdx.x & 31;
    const bool isk = (blockIdx.y == 4);
    const int h = isk ? warp : blockIdx.y * 8 + warp;
    const int nheads = isk ? NKV : NH;
    const float* w = isk ? kw : qw;
    float* buf = isk ? kb : qb;

    float* p = buf + (size_t)t * nheads * HD + h * HD;
    float a = p[lane];
    float b = p[lane + 32];

    float ss = a * a + b * b;
#pragma unroll
    for (int o = 16; o; o >>= 1) ss += __shfl_xor_sync(0xffffffffu, ss, o);
    float inv = rsqrtf(ss * (1.0f / HD) + 1e-6f);

    a *= inv * w[lane];
    b *= inv * w[lane + 32];

    float c0 = cosb[t * HD + lane];
    float s0 = sinb[t * HD + lane];
    float c1 = cosb[t * HD + lane + 32];
    float s1 = sinb[t * HD + lane + 32];

    p[lane]      = a * c0 - b * s0;
    p[lane + 32] = b * c1 + a * s1;
}

// ---------------------------------------------------------------------------
// Tensor-core flash attention (tf32 legacy mma); output written as fp16.
// ---------------------------------------------------------------------------
#define ATP 68
__global__ __launch_bounds__(128) void attn_tc(const float* __restrict__ q,
                                               const float* __restrict__ k,
                                               const float* __restrict__ v,
                                               __half* __restrict__ out) {
    extern __shared__ float sm[];
    float* Ks = sm;
    float* Vs = sm + 64 * ATP;
    float* Ps = sm + 2 * 64 * ATP;

    const int qt = blockIdx.x;
    const int h  = blockIdx.y;
    const int kvh = h >> 2;
    const int tid = threadIdx.x;
    const int lane = tid & 31;
    const int warp = tid >> 5;
    const int g = lane >> 2;
    const int tq = lane & 3;
    const int wr = warp * 16;
    const int row0 = wr + g;
    const int row1 = wr + 8 + g;

#pragma unroll
    for (int l = 0; l < 8; l++) {
        int idx = tid + l * 128;
        int r = idx >> 4;
        int c4 = idx & 15;
        float4 qv = *(const float4*)&q[(size_t)(qt * 64 + r) * (NH * HD) +
                                       h * HD + c4 * 4];
        float* d = &Ks[r * ATP + c4 * 4];
        d[0] = qv.x; d[1] = qv.y; d[2] = qv.z; d[3] = qv.w;
    }
    __syncthreads();

    uint32_t qf[8][4];
#pragma unroll
    for (int ks = 0; ks < 8; ks++) {
        qf[ks][0] = f2tf32(Ks[row0 * ATP + ks * 8 + tq]);
        qf[ks][1] = f2tf32(Ks[row1 * ATP + ks * 8 + tq]);
        qf[ks][2] = f2tf32(Ks[row0 * ATP + ks * 8 + tq + 4]);
        qf[ks][3] = f2tf32(Ks[row1 * ATP + ks * 8 + tq + 4]);
    }

    float m0 = -1e30f, m1 = -1e30f, l0 = 0.0f, l1 = 0.0f;
    float oacc[8][4];
#pragma unroll
    for (int nt = 0; nt < 8; nt++)
#pragma unroll
        for (int r = 0; r < 4; r++) oacc[nt][r] = 0.0f;

    for (int s = 0; s <= qt; s++) {
        __syncthreads();
#pragma unroll
        for (int l = 0; l < 8; l++) {
            int idx = tid + l * 128;
            int c = idx >> 4;
            int d4 = idx & 15;
            size_t gk = (size_t)(s * 64 + c) * (NKV * HD) + kvh * HD + d4 * 4;
            float4 kv4 = *(const float4*)&k[gk];
            float4 vv4 = *(const float4*)&v[gk];
            float* dk = &Ks[c * ATP + d4 * 4];
            dk[0] = kv4.x; dk[1] = kv4.y; dk[2] = kv4.z; dk[3] = kv4.w;
            float* dv = &Vs[c * ATP + d4 * 4];
            dv[0] = vv4.x; dv[1] = vv4.y; dv[2] = vv4.z; dv[3] = vv4.w;
        }
        __syncthreads();

        float sa[8][4];
#pragma unroll
        for (int nt = 0; nt < 8; nt++) {
#pragma unroll
            for (int r = 0; r < 4; r++) sa[nt][r] = 0.0f;
#pragma unroll
            for (int ks = 0; ks < 8; ks++) {
                uint32_t bf[2];
                bf[0] = f2tf32(Ks[(nt * 8 + g) * ATP + ks * 8 + tq]);
                bf[1] = f2tf32(Ks[(nt * 8 + g) * ATP + ks * 8 + tq + 4]);
                mma_tf32(sa[nt], qf[ks], bf);
            }
        }

        const bool diag = (s == qt);
        float rm0 = -1e30f, rm1 = -1e30f;
#pragma unroll
        for (int nt = 0; nt < 8; nt++) {
            int c0i = nt * 8 + 2 * tq;
#pragma unroll
            for (int j = 0; j < 2; j++) {
                float v0 = sa[nt][j] * 0.125f;
                float v1 = sa[nt][2 + j] * 0.125f;
                if (diag && (c0i + j > row0)) v0 = -1e30f;
                if (diag && (c0i + j > row1)) v1 = -1e30f;
                sa[nt][j] = v0;
                sa[nt][2 + j] = v1;
                rm0 = fmaxf(rm0, v0);
                rm1 = fmaxf(rm1, v1);
            }
        }
#pragma unroll
        for (int o = 1; o < 4; o <<= 1) {
            rm0 = fmaxf(rm0, __shfl_xor_sync(0xffffffffu, rm0, o));
            rm1 = fmaxf(rm1, __shfl_xor_sync(0xffffffffu, rm1, o));
        }
        float nm0 = fmaxf(m0, rm0), nm1 = fmaxf(m1, rm1);
        float cr0 = __expf(m0 - nm0), cr1 = __expf(m1 - nm1);
        m0 = nm0; m1 = nm1;
        float rs0 = 0.0f, rs1 = 0.0f;
#pragma unroll
        for (int nt = 0; nt < 8; nt++) {
#pragma unroll
            for (int j = 0; j < 2; j++) {
                float p0 = __expf(sa[nt][j] - m0);
                float p1 = __expf(sa[nt][2 + j] - m1);
                sa[nt][j] = p0;
                sa[nt][2 + j] = p1;
                rs0 += p0;
                rs1 += p1;
            }
        }
#pragma unroll
        for (int o = 1; o < 4; o <<= 1) {
            rs0 += __shfl_xor_sync(0xffffffffu, rs0, o);
            rs1 += __shfl_xor_sync(0xffffffffu, rs1, o);
        }
        l0 = l0 * cr0 + rs0;
        l1 = l1 * cr1 + rs1;
#pragma unroll
        for (int nt = 0; nt < 8; nt++) {
            oacc[nt][0] *= cr0; oacc[nt][1] *= cr0;
            oacc[nt][2] *= cr1; oacc[nt][3] *= cr1;
        }

#pragma unroll
        for (int nt = 0; nt < 8; nt++) {
            int c0i = nt * 8 + 2 * tq;
            Ps[row0 * ATP + c0i]     = sa[nt][0];
            Ps[row0 * ATP + c0i + 1] = sa[nt][1];
            Ps[row1 * ATP + c0i]     = sa[nt][2];
            Ps[row1 * ATP + c0i + 1] = sa[nt][3];
        }
        __syncwarp();

#pragma unroll
        for (int ks = 0; ks < 8; ks++) {
            uint32_t af[4];
            af[0] = f2tf32(Ps[row0 * ATP + ks * 8 + tq]);
            af[1] = f2tf32(Ps[row1 * ATP + ks * 8 + tq]);
            af[2] = f2tf32(Ps[row0 * ATP + ks * 8 + tq + 4]);
            af[3] = f2tf32(Ps[row1 * ATP + ks * 8 + tq + 4]);
#pragma unroll
            for (int nt = 0; nt < 8; nt++) {
                uint32_t bf[2];
                bf[0] = f2tf32(Vs[(ks * 8 + tq) * ATP + nt * 8 + g]);
                bf[1] = f2tf32(Vs[(ks * 8 + tq + 4) * ATP + nt * 8 + g]);
                mma_tf32(oacc[nt], af, bf);
            }
        }
    }

    float inv0 = 1.0f / l0, inv1 = 1.0f / l1;
#pragma unroll
    for (int nt = 0; nt < 8; nt++) {
        int col = h * HD + nt * 8 + 2 * tq;
        *(__half2*)&out[(size_t)(qt * 64 + row0) * (NH * HD) + col] =
            __floats2half2_rn(oacc[nt][0] * inv0, oacc[nt][1] * inv0);
        *(__half2*)&out[(size_t)(qt * 64 + row1) * (NH * HD) + col] =
            __floats2half2_rn(oacc[nt][2] * inv1, oacc[nt][3] * inv1);
    }
}

// ---------------------------------------------------------------------------
// Inputs: 0=x 1=scale_x 2=mask 3=cos 4=scale_cos 5=sin 6=scale_sin
//         7=Wq 8=Wk 9=Wv 10=Wo 11=q_norm_w 12=k_norm_w
// ---------------------------------------------------------------------------
extern "C" void kernel_launch(void* const* d_in, const int* in_sizes, int n_in,
                              void* d_out, int out_size) {
    const float* x    = (const float*)d_in[0];
    const float* cosb = (const float*)d_in[3];
    const float* sinb = (const float*)d_in[5];
    const float* Wq   = (const float*)d_in[7];
    const float* Wk   = (const float*)d_in[8];
    const float* Wv   = (const float*)d_in[9];
    const float* Wo   = (const float*)d_in[10];
    const float* qw   = (const float*)d_in[11];
    const float* kw   = (const float*)d_in[12];
    float* out = (float*)d_out;

    float *qb, *kb, *vb;
    __half *abh, *woh;
    cudaGetSymbolAddress((void**)&qb, g_q);
    cudaGetSymbolAddress((void**)&kb, g_k);
    cudaGetSymbolAddress((void**)&vb, g_v);
    cudaGetSymbolAddress((void**)&abh, g_abh);
    cudaGetSymbolAddress((void**)&woh, g_woh);

    const int gsmem = 65536;
    cudaFuncSetAttribute(gemm_qkv_h,
                         cudaFuncAttributeMaxDynamicSharedMemorySize, gsmem);
    cudaFuncSetAttribute(gemm_h,
                         cudaFuncAttributeMaxDynamicSharedMemorySize, gsmem);
    const int asmem = 3 * 64 * ATP * (int)sizeof(float);
    cudaFuncSetAttribute(attn_tc,
                         cudaFuncAttributeMaxDynamicSharedMemorySize, asmem);

    // fp32 -> fp16 conversion of x and all weights (12M elems)
    cvt_all<<<12288, 256>>>(x, Wq, Wk, Wv, Wo);

    // Fused QKV projection (fp16 TC, cp.async + ldmatrix)
    gemm_qkv_h<<<dim3(24, 8), 256, gsmem>>>(qb, kb, vb);

    // RMSNorm + RoPE (q + k fused)
    norm_rope2<<<dim3(T_TOK, 5), 256>>>(qb, kb, qw, kw, cosb, sinb);

    // Causal GQA attention (tf32 legacy mma), fp16 output
    attn_tc<<<dim3(16, 32), 128, asmem>>>(qb, kb, vb, abh);

    // Output projection (fp16 TC)
    gemm_h<<<dim3(16, 8), 256, gsmem>>>(abh, woh, out, DIN, NH * HD);
}

// round 7
// speedup vs baseline: 8.3923x; 1.3589x over previous
#include <cuda_runtime.h>
#include <cuda_fp16.h>
#include <stdint.h>
#include <math.h>

#define T_TOK 1024
#define DIN   2048
#define NH    32
#define NKV   8
#define HD    64

__device__ float g_q[T_TOK * NH * HD];
__device__ float g_k[T_TOK * NKV * HD];
__device__ __half g_qa[T_TOK * NH * HD];   // fp16 q (scaled by 0.125)
__device__ __half g_ka[T_TOK * NKV * HD];  // fp16 k
__device__ __half g_va[T_TOK * NKV * HD];  // fp16 v (from GEMM epilogue)
__device__ __half g_xh[T_TOK * DIN];
__device__ __half g_wqh[NH * HD * DIN];
__device__ __half g_wkh[NKV * HD * DIN];
__device__ __half g_wvh[NKV * HD * DIN];
__device__ __half g_woh[DIN * NH * HD];
__device__ __half g_abh[T_TOK * NH * HD];

// ---------------------------------------------------------------------------
// asm helpers
// ---------------------------------------------------------------------------
__device__ __forceinline__ uint32_t smem_u32(const void* p) {
    uint32_t a;
    asm("{ .reg .u64 t; cvta.to.shared.u64 t, %1; cvt.u32.u64 %0, t; }"
        : "=r"(a) : "l"(p));
    return a;
}

__device__ __forceinline__ void mma_f16(float* c, const uint32_t* a,
                                        const uint32_t* b) {
    asm volatile(
        "mma.sync.aligned.m16n8k16.row.col.f32.f16.f16.f32 "
        "{%0,%1,%2,%3},{%4,%5,%6,%7},{%8,%9},{%0,%1,%2,%3};"
        : "+f"(c[0]), "+f"(c[1]), "+f"(c[2]), "+f"(c[3])
        : "r"(a[0]), "r"(a[1]), "r"(a[2]), "r"(a[3]), "r"(b[0]), "r"(b[1]));
}

__device__ __forceinline__ void ldsm_x4(uint32_t* r, uint32_t addr) {
    asm volatile(
        "ldmatrix.sync.aligned.m8n8.x4.shared.b16 {%0,%1,%2,%3}, [%4];"
        : "=r"(r[0]), "=r"(r[1]), "=r"(r[2]), "=r"(r[3]) : "r"(addr));
}

__device__ __forceinline__ void ldsm_x4_t(uint32_t* r, uint32_t addr) {
    asm volatile(
        "ldmatrix.sync.aligned.m8n8.x4.trans.shared.b16 {%0,%1,%2,%3}, [%4];"
        : "=r"(r[0]), "=r"(r[1]), "=r"(r[2]), "=r"(r[3]) : "r"(addr));
}

__device__ __forceinline__ void cp16(uint32_t d, const void* s) {
    asm volatile("cp.async.cg.shared.global [%0], [%1], 16;"
                 :: "r"(d), "l"(s));
}
__device__ __forceinline__ void cp_commit() {
    asm volatile("cp.async.commit_group;");
}
template <int N>
__device__ __forceinline__ void cp_wait() {
    asm volatile("cp.async.wait_group %0;" :: "n"(N));
}

__device__ __forceinline__ uint32_t h2pack(float a, float b) {
    __half2 h = __floats2half2_rn(a, b);
    return *(uint32_t*)&h;
}

#define SW128(o) ((o) ^ (((o) >> 3) & 0x70))

// ---------------------------------------------------------------------------
// fp32 -> fp16 convert (x, Wq, Wk, Wv, Wo): 12M elems, 4 per thread.
// ---------------------------------------------------------------------------
__global__ __launch_bounds__(256) void cvt_all(const float* __restrict__ x,
                                               const float* __restrict__ Wq,
                                               const float* __restrict__ Wk,
                                               const float* __restrict__ Wv,
                                               const float* __restrict__ Wo) {
    const size_t e = ((size_t)blockIdx.x * 256 + threadIdx.x) * 4;
    const float* src;
    __half* dst;
    size_t base;
    if (e < 2097152)        { src = x;  dst = g_xh;  base = 0; }
    else if (e < 6291456)   { src = Wq; dst = g_wqh; base = 2097152; }
    else if (e < 7340032)   { src = Wk; dst = g_wkh; base = 6291456; }
    else if (e < 8388608)   { src = Wv; dst = g_wvh; base = 7340032; }
    else                    { src = Wo; dst = g_woh; base = 8388608; }
    const size_t o = e - base;
    float4 v = *(const float4*)&src[o];
    *(__half2*)&dst[o]     = __floats2half2_rn(v.x, v.y);
    *(__half2*)&dst[o + 2] = __floats2half2_rn(v.z, v.w);
}

// ---------------------------------------------------------------------------
// fp16 GEMM via cp.async + ldmatrix (as R6), optional fp16 epilogue (Ch).
// CTA tile 128x128, 256 thr, warp tile 64x32, K-chunk 64, 2-stage pipeline.
// ---------------------------------------------------------------------------
__device__ __forceinline__ void gemm_tile_h(const __half* __restrict__ A,
                                            const __half* __restrict__ B,
                                            float* __restrict__ C,
                                            __half* __restrict__ Ch,
                                            int N, int K, int bm, int bn,
                                            char* smem) {
    const uint32_t sbase = smem_u32(smem);
    const int tid  = threadIdx.x;
    const int lane = tid & 31;
    const int warp = tid >> 5;
    const int g    = lane >> 2;
    const int tq   = lane & 3;
    const int wm   = warp & 1;
    const int wn   = warp >> 1;
    const int quad = lane >> 3;
    const int lr   = lane & 7;
    const int ldrow = tid >> 3;
    const int ldc16 = tid & 7;

    auto stage = [&](int k0, int buf) {
        uint32_t dA = sbase + buf * 32768;
        uint32_t dB = dA + 16384;
#pragma unroll
        for (int p = 0; p < 4; p++) {
            int r = ldrow + p * 32;
            cp16(dA + SW128(r * 128 + ldc16 * 16),
                 &A[(size_t)(bm + r) * K + k0 + ldc16 * 8]);
            cp16(dB + SW128(r * 128 + ldc16 * 16),
                 &B[(size_t)(bn + r) * K + k0 + ldc16 * 8]);
        }
    };

    float acc[4][4][4];
#pragma unroll
    for (int mi = 0; mi < 4; mi++)
#pragma unroll
        for (int ni = 0; ni < 4; ni++)
#pragma unroll
            for (int r = 0; r < 4; r++) acc[mi][ni][r] = 0.0f;

    stage(0, 0);
    cp_commit();
    stage(64, 1);
    cp_commit();

    const int nch = K >> 6;
    for (int c = 0; c < nch; c++) {
        if (c == nch - 1) cp_wait<0>(); else cp_wait<1>();
        __syncthreads();
        const uint32_t sA = sbase + (c & 1) * 32768;
        const uint32_t sB = sA + 16384;

#pragma unroll
        for (int ks = 0; ks < 4; ks++) {
            uint32_t af[4][4];
#pragma unroll
            for (int mi = 0; mi < 4; mi++) {
                int row = wm * 64 + mi * 16 + (quad & 1) * 8 + lr;
                int colb = ks * 32 + (quad >> 1) * 16;
                ldsm_x4(af[mi], sA + SW128(row * 128 + colb));
            }
            uint32_t bf[2][4];
#pragma unroll
            for (int np = 0; np < 2; np++) {
                int row = wn * 32 + np * 16 + (quad >> 1) * 8 + lr;
                int colb = ks * 32 + (quad & 1) * 16;
                ldsm_x4(bf[np], sB + SW128(row * 128 + colb));
            }
#pragma unroll
            for (int mi = 0; mi < 4; mi++)
#pragma unroll
                for (int ni = 0; ni < 4; ni++)
                    mma_f16(acc[mi][ni], af[mi], &bf[ni >> 1][(ni & 1) * 2]);
        }

        if (c + 2 < nch) {
            __syncthreads();
            stage((c + 2) << 6, c & 1);
            cp_commit();
        }
    }

#pragma unroll
    for (int mi = 0; mi < 4; mi++)
#pragma unroll
        for (int ni = 0; ni < 4; ni++) {
            const int row = bm + wm * 64 + mi * 16 + g;
            const int col = bn + wn * 32 + ni * 8 + tq * 2;
            if (Ch) {
                *(__half2*)&Ch[(size_t)row * N + col] =
                    __floats2half2_rn(acc[mi][ni][0], acc[mi][ni][1]);
                *(__half2*)&Ch[(size_t)(row + 8) * N + col] =
                    __floats2half2_rn(acc[mi][ni][2], acc[mi][ni][3]);
            } else {
                *(float2*)&C[(size_t)row * N + col] =
                    make_float2(acc[mi][ni][0], acc[mi][ni][1]);
                *(float2*)&C[(size_t)(row + 8) * N + col] =
                    make_float2(acc[mi][ni][2], acc[mi][ni][3]);
            }
        }
}

__global__ __launch_bounds__(256) void gemm_h(const __half* __restrict__ A,
                                              const __half* __restrict__ B,
                                              float* __restrict__ C,
                                              int N, int K) {
    extern __shared__ char sh[];
    gemm_tile_h(A, B, C, nullptr, N, K, blockIdx.y * 128, blockIdx.x * 128, sh);
}

// Fused QKV: bx<16 -> Wq (fp32 out), bx<20 -> Wk (fp32), else Wv (fp16 out)
__global__ __launch_bounds__(256) void gemm_qkv_h(float* __restrict__ qb,
                                                  float* __restrict__ kb) {
    extern __shared__ char sh[];
    const int bx = blockIdx.x;
    const __half* B;
    float* C = nullptr;
    __half* Ch = nullptr;
    int N, bn;
    if (bx < 16)      { B = g_wqh; C = qb;  N = 2048; bn = bx * 128; }
    else if (bx < 20) { B = g_wkh; C = kb;  N = 512;  bn = (bx - 16) * 128; }
    else              { B = g_wvh; Ch = g_va; N = 512; bn = (bx - 20) * 128; }
    gemm_tile_h(g_xh, B, C, Ch, N, 2048, blockIdx.y * 128, bn, sh);
}

// ---------------------------------------------------------------------------
// RMSNorm + RoPE; reads fp32 q/k, writes fp16 (q scaled by 1/8 for attention).
// ---------------------------------------------------------------------------
__global__ __launch_bounds__(256) void norm_rope2(const float* __restrict__ qb,
                                                  const float* __restrict__ kb,
                                                  const float* __restrict__ qw,
                                                  const float* __restrict__ kw,
                                                  const float* __restrict__ cosb,
                                                  const float* __restrict__ sinb) {
    const int t = blockIdx.x;
    const int warp = threadIdx.x >> 5;
    const int lane = threadIdx.x & 31;
    const bool isk = (blockIdx.y == 4);
    const int h = isk ? warp : blockIdx.y * 8 + warp;
    const int nheads = isk ? NKV : NH;
    const float* w = isk ? kw : qw;
    const float* buf = isk ? kb : qb;
    __half* outh = isk ? g_ka : g_qa;
    const float sc = isk ? 1.0f : 0.125f;

    const float* p = buf + (size_t)t * nheads * HD + h * HD;
    float a = p[lane];
    float b = p[lane + 32];

    float ss = a * a + b * b;
#pragma unroll
    for (int o = 16; o; o >>= 1) ss += __shfl_xor_sync(0xffffffffu, ss, o);
    float inv = rsqrtf(ss * (1.0f / HD) + 1e-6f);

    a *= inv * w[lane];
    b *= inv * w[lane + 32];

    float c0 = cosb[t * HD + lane];
    float s0 = sinb[t * HD + lane];
    float c1 = cosb[t * HD + lane + 32];
    float s1 = sinb[t * HD + lane + 32];

    __half* po = outh + (size_t)t * nheads * HD + h * HD;
    po[lane]      = __float2half((a * c0 - b * s0) * sc);
    po[lane + 32] = __float2half((b * c1 + a * s1) * sc);
}

// ---------------------------------------------------------------------------
// fp16 flash attention: cp.async K/V pipeline + ldmatrix + m16n8k16 mma.
// CTA = (64-row q-tile, head), 4 warps x 16 rows. P stays in registers.
// Smem: Q 8KB + 2 stages x (K 8KB + V 8KB) = 40KB.
// ---------------------------------------------------------------------------
__global__ __launch_bounds__(128) void attn_h(__half* __restrict__ out) {
    extern __shared__ char sm[];
    const uint32_t sbase = smem_u32(sm);
    const uint32_t sQ = sbase;

    const int qt = blockIdx.x;
    const int h  = blockIdx.y;
    const int kvh = h >> 2;
    const int tid = threadIdx.x;
    const int lane = tid & 31;
    const int warp = tid >> 5;
    const int g = lane >> 2;
    const int tq = lane & 3;
    const int quad = lane >> 3;
    const int lr = lane & 7;
    const int wr = warp * 16;
    const int row0 = wr + g;
    const int row1 = wr + 8 + g;

    // stage Q (fp16, scaled) into smem
    {
        const __half* qp = g_qa + (size_t)(qt * 64) * (NH * HD) + h * HD;
#pragma unroll
        for (int l = 0; l < 4; l++) {
            int idx = tid + l * 128;
            int r = idx >> 3;
            int c16 = idx & 7;
            cp16(sQ + SW128(r * 128 + c16 * 16),
                 &qp[(size_t)r * (NH * HD) + c16 * 8]);
        }
    }
    cp_commit();

    auto stageKV = [&](int s, int buf) {
        uint32_t dK = sbase + 8192 + buf * 16384;
        uint32_t dV = dK + 8192;
        const __half* kp = g_ka + (size_t)(s * 64) * (NKV * HD) + kvh * HD;
        const __half* vp = g_va + (size_t)(s * 64) * (NKV * HD) + kvh * HD;
#pragma unroll
        for (int l = 0; l < 4; l++) {
            int idx = tid + l * 128;
            int c = idx >> 3;
            int c16 = idx & 7;
            uint32_t off = SW128(c * 128 + c16 * 16);
            cp16(dK + off, &kp[(size_t)c * (NKV * HD) + c16 * 8]);
            cp16(dV + off, &vp[(size_t)c * (NKV * HD) + c16 * 8]);
        }
    };

    stageKV(0, 0);
    cp_commit();
    if (qt >= 1) {
        stageKV(1, 1);
        cp_commit();
    }

    // Q fragments (register-resident)
    if (qt >= 1) cp_wait<2>(); else cp_wait<1>();
    __syncthreads();
    uint32_t qf[4][4];
#pragma unroll
    for (int ks = 0; ks < 4; ks++) {
        int row = wr + (quad & 1) * 8 + lr;
        int colb = ks * 32 + (quad >> 1) * 16;
        ldsm_x4(qf[ks], sQ + SW128(row * 128 + colb));
    }

    float m0 = -1e30f, m1 = -1e30f, l0 = 0.0f, l1 = 0.0f;
    float oacc[8][4];
#pragma unroll
    for (int nt = 0; nt < 8; nt++)
#pragma unroll
        for (int r = 0; r < 4; r++) oacc[nt][r] = 0.0f;

    for (int s = 0; s <= qt; s++) {
        if (s == qt) cp_wait<0>(); else cp_wait<1>();
        __syncthreads();
        const uint32_t sK = sbase + 8192 + (s & 1) * 16384;
        const uint32_t sV = sK + 8192;

        // S = Q K^T (q pre-scaled by 1/8)
        float sa[8][4];
#pragma unroll
        for (int nt = 0; nt < 8; nt++)
#pragma unroll
            for (int r = 0; r < 4; r++) sa[nt][r] = 0.0f;
#pragma unroll
        for (int ks = 0; ks < 4; ks++) {
#pragma unroll
            for (int np = 0; np < 4; np++) {
                uint32_t kb[4];
                int row = np * 16 + (quad >> 1) * 8 + lr;
                int colb = ks * 32 + (quad & 1) * 16;
                ldsm_x4(kb, sK + SW128(row * 128 + colb));
                mma_f16(sa[np * 2], qf[ks], &kb[0]);
                mma_f16(sa[np * 2 + 1], qf[ks], &kb[2]);
            }
        }

        // causal mask + online softmax
        const bool diag = (s == qt);
        float rm0 = -1e30f, rm1 = -1e30f;
#pragma unroll
        for (int nt = 0; nt < 8; nt++) {
            int c0i = nt * 8 + 2 * tq;
            if (diag) {
#pragma unroll
                for (int j = 0; j < 2; j++) {
                    if (c0i + j > row0) sa[nt][j] = -1e30f;
                    if (c0i + j > row1) sa[nt][2 + j] = -1e30f;
                }
            }
            rm0 = fmaxf(rm0, fmaxf(sa[nt][0], sa[nt][1]));
            rm1 = fmaxf(rm1, fmaxf(sa[nt][2], sa[nt][3]));
        }
#pragma unroll
        for (int o = 1; o < 4; o <<= 1) {
            rm0 = fmaxf(rm0, __shfl_xor_sync(0xffffffffu, rm0, o));
            rm1 = fmaxf(rm1, __shfl_xor_sync(0xffffffffu, rm1, o));
        }
        float nm0 = fmaxf(m0, rm0), nm1 = fmaxf(m1, rm1);
        float cr0 = __expf(m0 - nm0), cr1 = __expf(m1 - nm1);
        m0 = nm0; m1 = nm1;
        float rs0 = 0.0f, rs1 = 0.0f;
        uint32_t pr2[8][2];
#pragma unroll
        for (int nt = 0; nt < 8; nt++) {
            float p0 = __expf(sa[nt][0] - m0);
            float p1 = __expf(sa[nt][1] - m0);
            float p2 = __expf(sa[nt][2] - m1);
            float p3 = __expf(sa[nt][3] - m1);
            rs0 += p0 + p1;
            rs1 += p2 + p3;
            pr2[nt][0] = h2pack(p0, p1);
            pr2[nt][1] = h2pack(p2, p3);
        }
#pragma unroll
        for (int o = 1; o < 4; o <<= 1) {
            rs0 += __shfl_xor_sync(0xffffffffu, rs0, o);
            rs1 += __shfl_xor_sync(0xffffffffu, rs1, o);
        }
        l0 = l0 * cr0 + rs0;
        l1 = l1 * cr1 + rs1;
#pragma unroll
        for (int nt = 0; nt < 8; nt++) {
            oacc[nt][0] *= cr0; oacc[nt][1] *= cr0;
            oacc[nt][2] *= cr1; oacc[nt][3] *= cr1;
        }

        // O += P V (P from registers, V via ldmatrix.trans)
#pragma unroll
        for (int ks = 0; ks < 4; ks++) {
            uint32_t af[4] = {pr2[2 * ks][0], pr2[2 * ks][1],
                              pr2[2 * ks + 1][0], pr2[2 * ks + 1][1]};
#pragma unroll
            for (int np = 0; np < 4; np++) {
                uint32_t vb[4];
                int row = ks * 16 + (quad & 1) * 8 + lr;
                int colb = (np * 16 + (quad >> 1) * 8) * 2;
                ldsm_x4_t(vb, sV + SW128(row * 128 + colb));
                mma_f16(oacc[np * 2], af, &vb[0]);
                mma_f16(oacc[np * 2 + 1], af, &vb[2]);
            }
        }

        if (s + 2 <= qt) {
            __syncthreads();
            stageKV(s + 2, s & 1);
            cp_commit();
        }
    }

    // epilogue: normalize, write fp16
    float inv0 = 1.0f / l0, inv1 = 1.0f / l1;
#pragma unroll
    for (int nt = 0; nt < 8; nt++) {
        int col = h * HD + nt * 8 + 2 * tq;
        *(__half2*)&out[(size_t)(qt * 64 + row0) * (NH * HD) + col] =
            __floats2half2_rn(oacc[nt][0] * inv0, oacc[nt][1] * inv0);
        *(__half2*)&out[(size_t)(qt * 64 + row1) * (NH * HD) + col] =
            __floats2half2_rn(oacc[nt][2] * inv1, oacc[nt][3] * inv1);
    }
}

// ---------------------------------------------------------------------------
// Inputs: 0=x 1=scale_x 2=mask 3=cos 4=scale_cos 5=sin 6=scale_sin
//         7=Wq 8=Wk 9=Wv 10=Wo 11=q_norm_w 12=k_norm_w
// ---------------------------------------------------------------------------
extern "C" void kernel_launch(void* const* d_in, const int* in_sizes, int n_in,
                              void* d_out, int out_size) {
    const float* x    = (const float*)d_in[0];
    const float* cosb = (const float*)d_in[3];
    const float* sinb = (const float*)d_in[5];
    const float* Wq   = (const float*)d_in[7];
    const float* Wk   = (const float*)d_in[8];
    const float* Wv   = (const float*)d_in[9];
    const float* Wo   = (const float*)d_in[10];
    const float* qw   = (const float*)d_in[11];
    const float* kw   = (const float*)d_in[12];
    float* out = (float*)d_out;

    float *qb, *kb;
    __half *abh, *woh;
    cudaGetSymbolAddress((void**)&qb, g_q);
    cudaGetSymbolAddress((void**)&kb, g_k);
    cudaGetSymbolAddress((void**)&abh, g_abh);
    cudaGetSymbolAddress((void**)&woh, g_woh);

    const int gsmem = 65536;
    cudaFuncSetAttribute(gemm_qkv_h,
                         cudaFuncAttributeMaxDynamicSharedMemorySize, gsmem);
    cudaFuncSetAttribute(gemm_h,
                         cudaFuncAttributeMaxDynamicSharedMemorySize, gsmem);
    const int asmem = 8192 + 2 * 16384;  // Q + 2 KV stages = 40KB
    cudaFuncSetAttribute(attn_h,
                         cudaFuncAttributeMaxDynamicSharedMemorySize, asmem);

    // fp32 -> fp16 conversion (x + all weights)
    cvt_all<<<12288, 256>>>(x, Wq, Wk, Wv, Wo);

    // Fused QKV projection (V straight to fp16)
    gemm_qkv_h<<<dim3(24, 8), 256, gsmem>>>(qb, kb);

    // RMSNorm + RoPE -> fp16 q (pre-scaled), fp16 k
    norm_rope2<<<dim3(T_TOK, 5), 256>>>(qb, kb, qw, kw, cosb, sinb);

    // fp16 flash attention
    attn_h<<<dim3(16, 32), 128, asmem>>>(abh);

    // Output projection
    gemm_h<<<dim3(16, 8), 256, gsmem>>>(abh, woh, out, DIN, NH * HD);
}